// round 1
// baseline (speedup 1.0000x reference)
#include <cuda_runtime.h>
#include <math.h>

#define Bq   8
#define Lq   1024
#define DM   512
#define DIN  1024
#define DFF  2048
#define DS   16
#define DTR  32
#define MROWS (Bq*Lq)   /* 8192 token rows */

// ---------------- scratch (static __device__, no allocation) ----------------
__device__ float g_xz1 [MROWS*2*DIN];   // in_proj dir0: [xs | z]
__device__ float g_xz2 [MROWS*2*DIN];   // in_proj dir1
__device__ float g_xc1 [MROWS*DIN];     // conv+silu dir0
__device__ float g_xc2 [MROWS*DIN];
__device__ float g_xdbl1[MROWS*64];     // x_proj: [dt(32)|B(16)|C(16)]
__device__ float g_xdbl2[MROWS*64];
__device__ float g_dt1 [MROWS*DIN];     // softplus(dt_proj)
__device__ float g_dt2 [MROWS*DIN];
__device__ float g_y   [MROWS*2*DIN];   // gated scan outputs, [dir0 | dir1] per row
__device__ float g_o   [MROWS*DM];      // new_x = fwd + flip(bwd)
__device__ float g_xln [MROWS*DM];      // after LN1
__device__ float g_hff [MROWS*DFF];     // gelu(ff1)
__device__ float g_yff [MROWS*DM];      // ff2 + bias
__device__ float g_A   [2*DIN*DS];      // -exp(A_log), both dirs
__device__ float g_Wt  [2*DTR*DIN];     // dt_proj weight transposed, both dirs

// ---------------- prep: A = -exp(Alog); transpose dt_proj weights ----------------
__global__ void prep_kernel(const float* __restrict__ Alog1, const float* __restrict__ Alog2,
                            const float* __restrict__ Wdt1,  const float* __restrict__ Wdt2)
{
    int i = blockIdx.x*256 + threadIdx.x;              // 0..32767
    if (i < DIN*DS) {
        g_A[i]          = -__expf(Alog1[i]);
        g_A[DIN*DS + i] = -__expf(Alog2[i]);
    }
    if (i < DIN*DTR) {
        int d = i >> 5, k = i & 31;                    // Wdt is (DIN, DTR) row-major
        g_Wt[k*DIN + d]             = Wdt1[i];
        g_Wt[DTR*DIN + k*DIN + d]   = Wdt2[i];
    }
}

// ---------------- generic fp32 SGEMM:  C[m,n] = sum_k A[m,k]*B[n,k] ----------------
// BM=128 fixed, BN template (64 or 128), BK=16, 256 threads, 8 x (BN/16) microtile.
// EPI: 0 = store, 1 = accumulate into C, 2 = bias+exact-GELU, 3 = bias
__device__ __forceinline__ float gelu_exact(float x) {
    return 0.5f*x*(1.0f + erff(x*0.70710678118654752f));
}

template<int BN, int EPI>
__global__ __launch_bounds__(256)
void sgemm_kernel(const float* __restrict__ A, int lda,
                  const float* __restrict__ B, int ldb,
                  float* __restrict__ C, int ldc,
                  int K, const float* __restrict__ bias)
{
    __shared__ float As[16][128+4];
    __shared__ float Bs[16][BN+4];
    const int tid = threadIdx.x;
    const int tx = tid & 15, ty = tid >> 4;
    const int m0 = blockIdx.y * 128;
    const int n0 = blockIdx.x * BN;
    constexpr int NJ = BN/16;

    float acc[8][NJ];
#pragma unroll
    for (int i=0;i<8;i++)
#pragma unroll
        for (int j=0;j<NJ;j++) acc[i][j]=0.f;

    const float* Ap = A + (size_t)m0*lda;
    const float* Bp = B + (size_t)n0*ldb;

    for (int k0 = 0; k0 < K; k0 += 16) {
#pragma unroll
        for (int r=0;r<2;r++) {                       // A tile: 128x16 = 512 float4
            int v = tid + r*256;
            int m = v >> 2, kq = v & 3;
            const float4 f = *(const float4*)(Ap + (size_t)m*lda + k0 + kq*4);
            As[kq*4+0][m]=f.x; As[kq*4+1][m]=f.y; As[kq*4+2][m]=f.z; As[kq*4+3][m]=f.w;
        }
#pragma unroll
        for (int r=0;r<BN/64;r++) {                   // B tile: BNx16
            int v = tid + r*256;
            int n = v >> 2, kq = v & 3;
            const float4 f = *(const float4*)(Bp + (size_t)n*ldb + k0 + kq*4);
            Bs[kq*4+0][n]=f.x; Bs[kq*4+1][n]=f.y; Bs[kq*4+2][n]=f.z; Bs[kq*4+3][n]=f.w;
        }
        __syncthreads();
#pragma unroll
        for (int k=0;k<16;k++) {
            float a[8], bb[NJ];
#pragma unroll
            for (int i=0;i<8;i++) a[i] = As[k][ty + i*16];
#pragma unroll
            for (int j=0;j<NJ;j++) bb[j] = Bs[k][tx + j*16];
#pragma unroll
            for (int i=0;i<8;i++)
#pragma unroll
                for (int j=0;j<NJ;j++) acc[i][j] = fmaf(a[i], bb[j], acc[i][j]);
        }
        __syncthreads();
    }

#pragma unroll
    for (int i=0;i<8;i++) {
#pragma unroll
        for (int j=0;j<NJ;j++) {
            int m = m0 + ty + i*16, n = n0 + tx + j*16;
            size_t ci = (size_t)m*ldc + n;
            float v = acc[i][j];
            if (EPI==1) v += C[ci];
            if (EPI==2) { v += bias[n]; v = gelu_exact(v); }
            if (EPI==3) v += bias[n];
            C[ci] = v;
        }
    }
}

// ---------------- depthwise causal conv (k=4) + bias + SiLU, both dirs ----------------
// dir0: xc[t] = sum_k w[k]*xs[t-3+k]   (causal)
// dir1: xc[t] = sum_k w[k]*xs[t+3-k]   (causal on the time-flipped sequence)
__global__ __launch_bounds__(256)
void conv_kernel(const float* __restrict__ w1, const float* __restrict__ b1,
                 const float* __restrict__ w2, const float* __restrict__ b2)
{
    int dir = blockIdx.y;
    const float* xz = dir ? g_xz2 : g_xz1;
    const float* w  = dir ? w2 : w1;
    const float* cb = dir ? b2 : b1;
    float* xc       = dir ? g_xc2 : g_xc1;

    int idx = blockIdx.x*256 + threadIdx.x;           // (row, d)
    int d   = idx & (DIN-1);
    int row = idx >> 10;
    int t   = row & (Lq-1);
    float w0=w[d*4+0], w1_=w[d*4+1], w2_=w[d*4+2], w3=w[d*4+3];
    float s = cb[d];
    const float* base = xz + (size_t)row*(2*DIN) + d;
    if (dir == 0) {
        s += w3 * base[0];
        if (t >= 1) s += w2_ * base[-1*(2*DIN)];
        if (t >= 2) s += w1_ * base[-2*(2*DIN)];
        if (t >= 3) s += w0  * base[-3*(2*DIN)];
    } else {
        s += w3 * base[0];
        if (t <= Lq-2) s += w2_ * base[ 1*(2*DIN)];
        if (t <= Lq-3) s += w1_ * base[ 2*(2*DIN)];
        if (t <= Lq-4) s += w0  * base[ 3*(2*DIN)];
    }
    xc[(size_t)row*DIN + d] = s / (1.f + __expf(-s));  // SiLU
}

// ---------------- dt = softplus(dt_raw @ dtp_w^T + b), K=32, both dirs ----------------
__global__ __launch_bounds__(256)
void dt_kernel(const float* __restrict__ b1, const float* __restrict__ b2)
{
    int dir = blockIdx.y;
    const float* xdbl = dir ? g_xdbl2 : g_xdbl1;
    const float* Wt   = g_Wt + dir*DTR*DIN;
    const float* bias = dir ? b2 : b1;
    float* out        = dir ? g_dt2 : g_dt1;

    __shared__ float r[DTR];
    int row = blockIdx.x;
    if (threadIdx.x < DTR) r[threadIdx.x] = xdbl[(size_t)row*64 + threadIdx.x];
    __syncthreads();
#pragma unroll
    for (int q = 0; q < 4; q++) {
        int d = threadIdx.x + q*256;
        float s = bias[d];
#pragma unroll
        for (int k = 0; k < DTR; k++) s = fmaf(r[k], Wt[k*DIN + d], s);
        float sp = (s > 20.f) ? s : log1pf(__expf(s));
        out[(size_t)row*DIN + d] = sp;
    }
}

// ---------------- selective scan + D-skip + SiLU(z) gate, both dirs ----------------
// 4 states per lane, 8 channels per warp; dir1 iterates t backwards and stores
// at the original t (== flip of the flipped output).
__global__ __launch_bounds__(256)
void scan_kernel(const float* __restrict__ D1, const float* __restrict__ D2)
{
    int dir = blockIdx.y;
    const float* dt   = dir ? g_dt2  : g_dt1;
    const float* xc   = dir ? g_xc2  : g_xc1;
    const float* xdbl = dir ? g_xdbl2: g_xdbl1;
    const float* xz   = dir ? g_xz2  : g_xz1;
    const float* Aexp = g_A + dir*DIN*DS;
    const float* Dv_  = dir ? D2 : D1;

    int warp = threadIdx.x >> 5, lane = threadIdx.x & 31;
    int sg = lane & 3;                                 // state group (4 states)
    int c  = blockIdx.x*64 + warp*8 + (lane >> 2);     // global channel
    int b  = c >> 10, d = c & (DIN-1);

    const float4 a4 = *(const float4*)(Aexp + d*DS + sg*4);
    const float Dd = Dv_[d];
    float h0=0.f, h1=0.f, h2=0.f, h3=0.f;
    const int rbase = b*Lq;

    for (int i = 0; i < Lq; i++) {
        int t = dir ? (Lq-1-i) : i;
        size_t row = rbase + t;
        float dtv = dt[row*DIN + d];
        float uv  = xc[row*DIN + d];
        const float4 Bv = *(const float4*)(xdbl + row*64 + DTR + sg*4);
        const float4 Cv = *(const float4*)(xdbl + row*64 + DTR + DS + sg*4);
        float du = dtv*uv;
        h0 = fmaf(__expf(dtv*a4.x), h0, du*Bv.x);
        h1 = fmaf(__expf(dtv*a4.y), h1, du*Bv.y);
        h2 = fmaf(__expf(dtv*a4.z), h2, du*Bv.z);
        h3 = fmaf(__expf(dtv*a4.w), h3, du*Bv.w);
        float p = h0*Cv.x + h1*Cv.y + h2*Cv.z + h3*Cv.w;
        p += __shfl_xor_sync(0xffffffffu, p, 1);
        p += __shfl_xor_sync(0xffffffffu, p, 2);
        if (sg == 0) {
            float zv = xz[row*(2*DIN) + DIN + d];
            float yv = (p + uv*Dd) * (zv / (1.f + __expf(-zv)));
            g_y[row*(2*DIN) + dir*DIN + d] = yv;
        }
    }
}

// ---------------- LayerNorm: out = LN(a + b) * g + beta ; one warp per row ----------------
__global__ __launch_bounds__(256)
void ln_kernel(const float* __restrict__ a, const float* __restrict__ b,
               const float* __restrict__ g, const float* __restrict__ beta,
               float* __restrict__ out)
{
    int row  = blockIdx.x*8 + (threadIdx.x >> 5);
    int lane = threadIdx.x & 31;
    const float* pa = a + (size_t)row*DM;
    const float* pb = b + (size_t)row*DM;
    float v[16];
    float s = 0.f, s2 = 0.f;
#pragma unroll
    for (int i = 0; i < 16; i++) {
        int cix = lane + i*32;
        float x = pa[cix] + pb[cix];
        v[i] = x; s += x; s2 = fmaf(x, x, s2);
    }
#pragma unroll
    for (int off = 16; off > 0; off >>= 1) {
        s  += __shfl_xor_sync(0xffffffffu, s,  off);
        s2 += __shfl_xor_sync(0xffffffffu, s2, off);
    }
    float mean = s * (1.f/DM);
    float var  = s2 * (1.f/DM) - mean*mean;
    float inv  = rsqrtf(var + 1e-5f);
    float* po = out + (size_t)row*DM;
#pragma unroll
    for (int i = 0; i < 16; i++) {
        int cix = lane + i*32;
        po[cix] = (v[i]-mean)*inv*g[cix] + beta[cix];
    }
}

// ---------------- launch ----------------
extern "C" void kernel_launch(void* const* d_in, const int* in_sizes, int n_in,
                              void* d_out, int out_size)
{
    const float* x       = (const float*)d_in[0];
    const float* in1_w   = (const float*)d_in[1];
    const float* conv1_w = (const float*)d_in[2];
    const float* conv1_b = (const float*)d_in[3];
    const float* xp1_w   = (const float*)d_in[4];
    const float* dtp1_w  = (const float*)d_in[5];
    const float* dtp1_b  = (const float*)d_in[6];
    const float* Alog1   = (const float*)d_in[7];
    const float* D1      = (const float*)d_in[8];
    const float* outp1_w = (const float*)d_in[9];
    const float* in2_w   = (const float*)d_in[10];
    const float* conv2_w = (const float*)d_in[11];
    const float* conv2_b = (const float*)d_in[12];
    const float* xp2_w   = (const float*)d_in[13];
    const float* dtp2_w  = (const float*)d_in[14];
    const float* dtp2_b  = (const float*)d_in[15];
    const float* Alog2   = (const float*)d_in[16];
    const float* D2      = (const float*)d_in[17];
    const float* outp2_w = (const float*)d_in[18];
    const float* c1_w    = (const float*)d_in[19];
    const float* c1_b    = (const float*)d_in[20];
    const float* c2_w    = (const float*)d_in[21];
    const float* c2_b    = (const float*)d_in[22];
    const float* ln1_g   = (const float*)d_in[23];
    const float* ln1_b   = (const float*)d_in[24];
    const float* ln2_g   = (const float*)d_in[25];
    const float* ln2_b   = (const float*)d_in[26];
    float* out = (float*)d_out;

    float *xz1,*xz2,*xc1,*xc2,*xdbl1,*xdbl2,*yb,*o,*xln,*hff,*yff;
    cudaGetSymbolAddress((void**)&xz1,  g_xz1);
    cudaGetSymbolAddress((void**)&xz2,  g_xz2);
    cudaGetSymbolAddress((void**)&xc1,  g_xc1);
    cudaGetSymbolAddress((void**)&xc2,  g_xc2);
    cudaGetSymbolAddress((void**)&xdbl1,g_xdbl1);
    cudaGetSymbolAddress((void**)&xdbl2,g_xdbl2);
    cudaGetSymbolAddress((void**)&yb,   g_y);
    cudaGetSymbolAddress((void**)&o,    g_o);
    cudaGetSymbolAddress((void**)&xln,  g_xln);
    cudaGetSymbolAddress((void**)&hff,  g_hff);
    cudaGetSymbolAddress((void**)&yff,  g_yff);

    prep_kernel<<<128,256>>>(Alog1, Alog2, dtp1_w, dtp2_w);

    // in_proj, both dirs: (8192x2048) = x(8192x512) @ W^T
    {
        dim3 g(2*DIN/128, MROWS/128);
        sgemm_kernel<128,0><<<g,256>>>(x, DM, in1_w, DM, xz1, 2*DIN, DM, nullptr);
        sgemm_kernel<128,0><<<g,256>>>(x, DM, in2_w, DM, xz2, 2*DIN, DM, nullptr);
    }

    // depthwise conv + silu
    {
        dim3 g(MROWS*DIN/256, 2);
        conv_kernel<<<g,256>>>(conv1_w, conv1_b, conv2_w, conv2_b);
    }

    // x_proj: (8192x64) = xc @ xp_w^T, K=1024
    {
        dim3 g(64/64, MROWS/128);
        sgemm_kernel<64,0><<<g,256>>>(xc1, DIN, xp1_w, DIN, xdbl1, 64, DIN, nullptr);
        sgemm_kernel<64,0><<<g,256>>>(xc2, DIN, xp2_w, DIN, xdbl2, 64, DIN, nullptr);
    }

    // dt_proj + softplus
    {
        dim3 g(MROWS, 2);
        dt_kernel<<<g,256>>>(dtp1_b, dtp2_b);
    }

    // selective scan + gate (dir1 backwards, already un-flipped on store)
    {
        dim3 g(MROWS*DIN/ (64*1024) * 1024 / 1024, 2);   // = (128, 2)
        dim3 gs(Bq*DIN/64, 2);
        scan_kernel<<<gs,256>>>(D1, D2);
    }

    // out_proj both dirs, accumulated: o = y1 @ out1^T + y2 @ out2^T
    {
        dim3 g(DM/128, MROWS/128);
        sgemm_kernel<128,0><<<g,256>>>(yb,        2*DIN, outp1_w, DIN, o, DM, DIN, nullptr);
        sgemm_kernel<128,1><<<g,256>>>(yb + DIN,  2*DIN, outp2_w, DIN, o, DM, DIN, nullptr);
    }

    // LN1: xln = LN(o + x)
    ln_kernel<<<MROWS/8,256>>>(o, x, ln1_g, ln1_b, xln);

    // FFN
    {
        dim3 g1(DFF/128, MROWS/128);
        sgemm_kernel<128,2><<<g1,256>>>(xln, DM, c1_w, DM, hff, DFF, DM, c1_b);
        dim3 g2(DM/128, MROWS/128);
        sgemm_kernel<128,3><<<g2,256>>>(hff, DFF, c2_w, DFF, yff, DM, DFF, c2_b);
    }

    // LN2: out = LN(xln + yff)
    ln_kernel<<<MROWS/8,256>>>(xln, yff, ln2_g, ln2_b, out);
}

// round 3
// speedup vs baseline: 1.5840x; 1.5840x over previous
#include <cuda_runtime.h>
#include <cuda_bf16.h>
#include <math.h>
#include <stdint.h>

#define Bq   8
#define Lq   1024
#define DM   512
#define DIN  1024
#define DFF  2048
#define DS   16
#define DTR  32
#define MROWS (Bq*Lq)   /* 8192 token rows */

// ---------------- scratch (static __device__, no allocation) ----------------
__device__ float g_xz1 [MROWS*2*DIN];
__device__ float g_xz2 [MROWS*2*DIN];
__device__ float g_xc1 [MROWS*DIN];
__device__ float g_xc2 [MROWS*DIN];
__device__ float g_xdbl1[MROWS*64];
__device__ float g_xdbl2[MROWS*64];
__device__ float g_dt1 [MROWS*DIN];
__device__ float g_dt2 [MROWS*DIN];
__device__ float g_y   [MROWS*2*DIN];   // [dir0 | dir1] per row
__device__ float g_o   [MROWS*DM];
__device__ float g_xln [MROWS*DM];
__device__ float g_hff [MROWS*DFF];
__device__ float g_yff [MROWS*DM];
__device__ float g_A   [2*DIN*DS];
__device__ float g_Wt  [2*DTR*DIN];

// ======================= helpers =======================
__device__ __forceinline__ uint32_t smem_u32(const void* p) {
    uint32_t a;
    asm("{ .reg .u64 t; cvta.to.shared.u64 t, %1; cvt.u32.u64 %0, t; }" : "=r"(a) : "l"(p));
    return a;
}
__device__ __forceinline__ void ldmx4(uint32_t* r, uint32_t addr) {
    asm volatile("ldmatrix.sync.aligned.m8n8.x4.shared.b16 {%0,%1,%2,%3}, [%4];"
                 : "=r"(r[0]), "=r"(r[1]), "=r"(r[2]), "=r"(r[3]) : "r"(addr));
}
__device__ __forceinline__ void ldmx2(uint32_t* r, uint32_t addr) {
    asm volatile("ldmatrix.sync.aligned.m8n8.x2.shared.b16 {%0,%1}, [%2];"
                 : "=r"(r[0]), "=r"(r[1]) : "r"(addr));
}
__device__ __forceinline__ void hmma(float* d, const uint32_t* a, const uint32_t* b) {
    asm volatile(
        "mma.sync.aligned.m16n8k16.row.col.f32.bf16.bf16.f32 "
        "{%0,%1,%2,%3}, {%4,%5,%6,%7}, {%8,%9}, {%0,%1,%2,%3};"
        : "+f"(d[0]), "+f"(d[1]), "+f"(d[2]), "+f"(d[3])
        : "r"(a[0]), "r"(a[1]), "r"(a[2]), "r"(a[3]), "r"(b[0]), "r"(b[1]));
}
__device__ __forceinline__ uint32_t pkbf2(float a, float b) {
    __nv_bfloat162 t = __floats2bfloat162_rn(a, b);
    return reinterpret_cast<uint32_t&>(t);
}
__device__ __forceinline__ void split8(float4 f0, float4 f1, uint4& h, uint4& l) {
    float v[8] = {f0.x, f0.y, f0.z, f0.w, f1.x, f1.y, f1.z, f1.w};
    float r[8];
#pragma unroll
    for (int j = 0; j < 8; j++)
        r[j] = v[j] - __bfloat162float(__float2bfloat16_rn(v[j]));
    h.x = pkbf2(v[0], v[1]); h.y = pkbf2(v[2], v[3]);
    h.z = pkbf2(v[4], v[5]); h.w = pkbf2(v[6], v[7]);
    l.x = pkbf2(r[0], r[1]); l.y = pkbf2(r[2], r[3]);
    l.z = pkbf2(r[4], r[5]); l.w = pkbf2(r[6], r[7]);
}
__device__ __forceinline__ float gelu_exact(float x) {
    return 0.5f * x * (1.0f + erff(x * 0.70710678118654752f));
}

// ======================= HMMA bf16 split GEMM =======================
// C[m,n] = sum_k A[m,k]*B[n,k], fp32 I/O, bf16 hi/lo 3-term emulation.
// Block tile 128 x BN, BK=32. Warp grid 2(m) x BN/32(n), warp tile 64x32.
// EPI: 0 = store, 2 = bias+GELU, 3 = bias.   B switches to B2 at kSplit.
template<int BN, int EPI>
__global__ __launch_bounds__(64*(BN/32))
void tgemm(const float* __restrict__ A, int lda,
           const float* __restrict__ B, const float* __restrict__ B2,
           int ldb, int kSplit,
           float* __restrict__ C, int ldc, int K,
           const float* __restrict__ bias)
{
    constexpr int WN = BN / 32;       // warps along n
    constexpr int T  = 64 * WN;       // threads
    constexpr int PK = 40;            // padded k stride (elements)

    __shared__ __align__(16) __nv_bfloat16 sA[2][128 * PK];  // [hi|lo]
    __shared__ __align__(16) __nv_bfloat16 sB[2][BN  * PK];

    const int tid  = threadIdx.x;
    const int wid  = tid >> 5, lane = tid & 31;
    const int warp_m = wid & 1, warp_n = wid >> 1;
    const int m0 = blockIdx.y * 128;
    const int n0 = blockIdx.x * BN;

    float acc[4][4][4];
#pragma unroll
    for (int i = 0; i < 4; i++)
#pragma unroll
        for (int j = 0; j < 4; j++)
#pragma unroll
            for (int q = 0; q < 4; q++) acc[i][j][q] = 0.f;

    const uint32_t aHi = smem_u32(sA[0]), aLo = smem_u32(sA[1]);
    const uint32_t bHi = smem_u32(sB[0]), bLo = smem_u32(sB[1]);

    // ldmatrix per-thread offsets
    const int rA  = (lane & 15);            // A: x4, 16 rows
    const int cA  = (lane >> 4) * 8;
    const int l2  = lane & 15;              // B: x2, 8 rows * 2 mats
    const int rB  = l2 & 7;
    const int cB  = (l2 >> 3) * 8;

    for (int k0 = 0; k0 < K; k0 += 32) {
        // ---- A tile: 128x32 fp32 -> bf16 hi/lo ----
#pragma unroll
        for (int i = 0; i < (128*32)/(T*8); i++) {
            int g = tid + i * T;
            int row = g >> 2, kg = g & 3;
            const float4* p = reinterpret_cast<const float4*>(
                A + (size_t)(m0 + row) * lda + k0 + kg * 8);
            uint4 h, l;
            split8(p[0], p[1], h, l);
            int off = row * PK + kg * 8;
            *reinterpret_cast<uint4*>(&sA[0][off]) = h;
            *reinterpret_cast<uint4*>(&sA[1][off]) = l;
        }
        // ---- B tile: BNx32 ----
        const float* Bp = (k0 < kSplit) ? B : B2;
        int kb = (k0 < kSplit) ? k0 : (k0 - kSplit);
#pragma unroll
        for (int i = 0; i < (BN*32)/(T*8); i++) {
            int g = tid + i * T;
            int row = g >> 2, kg = g & 3;
            const float4* p = reinterpret_cast<const float4*>(
                Bp + (size_t)(n0 + row) * ldb + kb + kg * 8);
            uint4 h, l;
            split8(p[0], p[1], h, l);
            int off = row * PK + kg * 8;
            *reinterpret_cast<uint4*>(&sB[0][off]) = h;
            *reinterpret_cast<uint4*>(&sB[1][off]) = l;
        }
        __syncthreads();

#pragma unroll
        for (int kk = 0; kk < 32; kk += 16) {
            uint32_t Ah[4][4], Bh[4][2];
            const int aoff = kk + cA;
            const int boff = kk + cB;
#pragma unroll
            for (int mf = 0; mf < 4; mf++)
                ldmx4(Ah[mf], aHi + ((warp_m*64 + mf*16 + rA) * PK + aoff) * 2);
#pragma unroll
            for (int nf = 0; nf < 4; nf++)
                ldmx2(Bh[nf], bHi + ((warp_n*32 + nf*8 + rB) * PK + boff) * 2);
#pragma unroll
            for (int mf = 0; mf < 4; mf++)
#pragma unroll
                for (int nf = 0; nf < 4; nf++)
                    hmma(acc[mf][nf], Ah[mf], Bh[nf]);

            uint32_t Bl[4][2];
#pragma unroll
            for (int nf = 0; nf < 4; nf++)
                ldmx2(Bl[nf], bLo + ((warp_n*32 + nf*8 + rB) * PK + boff) * 2);
#pragma unroll
            for (int mf = 0; mf < 4; mf++)
#pragma unroll
                for (int nf = 0; nf < 4; nf++)
                    hmma(acc[mf][nf], Ah[mf], Bl[nf]);

            uint32_t Al[4][4];
#pragma unroll
            for (int mf = 0; mf < 4; mf++)
                ldmx4(Al[mf], aLo + ((warp_m*64 + mf*16 + rA) * PK + aoff) * 2);
#pragma unroll
            for (int mf = 0; mf < 4; mf++)
#pragma unroll
                for (int nf = 0; nf < 4; nf++)
                    hmma(acc[mf][nf], Al[mf], Bh[nf]);
        }
        __syncthreads();
    }

    // ---- epilogue: direct float2 stores (32B sectors per quad) ----
    const int rr = lane >> 2;
    const int cc = (lane & 3) * 2;
#pragma unroll
    for (int mf = 0; mf < 4; mf++) {
#pragma unroll
        for (int nf = 0; nf < 4; nf++) {
            int col = n0 + warp_n*32 + nf*8 + cc;
            float b0 = 0.f, b1 = 0.f;
            if (EPI == 2 || EPI == 3) { b0 = bias[col]; b1 = bias[col+1]; }
#pragma unroll
            for (int h = 0; h < 2; h++) {
                int row = m0 + warp_m*64 + mf*16 + rr + h*8;
                float v0 = acc[mf][nf][h*2+0];
                float v1 = acc[mf][nf][h*2+1];
                if (EPI == 2) { v0 = gelu_exact(v0 + b0); v1 = gelu_exact(v1 + b1); }
                if (EPI == 3) { v0 += b0; v1 += b1; }
                float2 st = make_float2(v0, v1);
                *reinterpret_cast<float2*>(C + (size_t)row * ldc + col) = st;
            }
        }
    }
}

// ---------------- prep: A = -exp(Alog); transpose dt_proj weights ----------------
__global__ void prep_kernel(const float* __restrict__ Alog1, const float* __restrict__ Alog2,
                            const float* __restrict__ Wdt1,  const float* __restrict__ Wdt2)
{
    int i = blockIdx.x*256 + threadIdx.x;
    if (i < DIN*DS) {
        g_A[i]          = -__expf(Alog1[i]);
        g_A[DIN*DS + i] = -__expf(Alog2[i]);
    }
    if (i < DIN*DTR) {
        int d = i >> 5, k = i & 31;
        g_Wt[k*DIN + d]           = Wdt1[i];
        g_Wt[DTR*DIN + k*DIN + d] = Wdt2[i];
    }
}

// ---------------- depthwise causal conv (k=4) + bias + SiLU ----------------
__global__ __launch_bounds__(256)
void conv_kernel(const float* __restrict__ w1, const float* __restrict__ b1,
                 const float* __restrict__ w2, const float* __restrict__ b2)
{
    int dir = blockIdx.y;
    const float* xz = dir ? g_xz2 : g_xz1;
    const float* w  = dir ? w2 : w1;
    const float* cb = dir ? b2 : b1;
    float* xc       = dir ? g_xc2 : g_xc1;

    int idx = blockIdx.x*256 + threadIdx.x;
    int d   = idx & (DIN-1);
    int row = idx >> 10;
    int t   = row & (Lq-1);
    float w0=w[d*4+0], w1_=w[d*4+1], w2_=w[d*4+2], w3=w[d*4+3];
    float s = cb[d];
    const float* base = xz + (size_t)row*(2*DIN) + d;
    if (dir == 0) {
        s += w3 * base[0];
        if (t >= 1) s += w2_ * base[-1*(2*DIN)];
        if (t >= 2) s += w1_ * base[-2*(2*DIN)];
        if (t >= 3) s += w0  * base[-3*(2*DIN)];
    } else {
        s += w3 * base[0];
        if (t <= Lq-2) s += w2_ * base[ 1*(2*DIN)];
        if (t <= Lq-3) s += w1_ * base[ 2*(2*DIN)];
        if (t <= Lq-4) s += w0  * base[ 3*(2*DIN)];
    }
    xc[(size_t)row*DIN + d] = s / (1.f + __expf(-s));
}

// ---------------- dt = softplus(dt_raw @ dtp_w^T + b) ----------------
__global__ __launch_bounds__(256)
void dt_kernel(const float* __restrict__ b1, const float* __restrict__ b2)
{
    int dir = blockIdx.y;
    const float* xdbl = dir ? g_xdbl2 : g_xdbl1;
    const float* Wt   = g_Wt + dir*DTR*DIN;
    const float* bias = dir ? b2 : b1;
    float* out        = dir ? g_dt2 : g_dt1;

    __shared__ float r[DTR];
    int row = blockIdx.x;
    if (threadIdx.x < DTR) r[threadIdx.x] = xdbl[(size_t)row*64 + threadIdx.x];
    __syncthreads();
#pragma unroll
    for (int q = 0; q < 4; q++) {
        int d = threadIdx.x + q*256;
        float s = bias[d];
#pragma unroll
        for (int k = 0; k < DTR; k++) s = fmaf(r[k], Wt[k*DIN + d], s);
        float sp = (s > 20.f) ? s : log1pf(__expf(s));
        out[(size_t)row*DIN + d] = sp;
    }
}

// ---------------- selective scan + D-skip + SiLU(z) gate ----------------
__global__ __launch_bounds__(256)
void scan_kernel(const float* __restrict__ D1, const float* __restrict__ D2)
{
    int dir = blockIdx.y;
    const float* dt   = dir ? g_dt2  : g_dt1;
    const float* xc   = dir ? g_xc2  : g_xc1;
    const float* xdbl = dir ? g_xdbl2: g_xdbl1;
    const float* xz   = dir ? g_xz2  : g_xz1;
    const float* Aexp = g_A + dir*DIN*DS;
    const float* Dv_  = dir ? D2 : D1;

    int warp = threadIdx.x >> 5, lane = threadIdx.x & 31;
    int sg = lane & 3;
    int c  = blockIdx.x*64 + warp*8 + (lane >> 2);
    int b  = c >> 10, d = c & (DIN-1);

    const float4 a4 = *(const float4*)(Aexp + d*DS + sg*4);
    const float Dd = Dv_[d];
    float h0=0.f, h1=0.f, h2=0.f, h3=0.f;
    const int rbase = b*Lq;

    for (int i = 0; i < Lq; i++) {
        int t = dir ? (Lq-1-i) : i;
        size_t row = rbase + t;
        float dtv = dt[row*DIN + d];
        float uv  = xc[row*DIN + d];
        const float4 Bv = *(const float4*)(xdbl + row*64 + DTR + sg*4);
        const float4 Cv = *(const float4*)(xdbl + row*64 + DTR + DS + sg*4);
        float du = dtv*uv;
        h0 = fmaf(__expf(dtv*a4.x), h0, du*Bv.x);
        h1 = fmaf(__expf(dtv*a4.y), h1, du*Bv.y);
        h2 = fmaf(__expf(dtv*a4.z), h2, du*Bv.z);
        h3 = fmaf(__expf(dtv*a4.w), h3, du*Bv.w);
        float p = h0*Cv.x + h1*Cv.y + h2*Cv.z + h3*Cv.w;
        p += __shfl_xor_sync(0xffffffffu, p, 1);
        p += __shfl_xor_sync(0xffffffffu, p, 2);
        if (sg == 0) {
            float zv = xz[row*(2*DIN) + DIN + d];
            float yv = (p + uv*Dd) * (zv / (1.f + __expf(-zv)));
            g_y[row*(2*DIN) + dir*DIN + d] = yv;
        }
    }
}

// ---------------- LayerNorm: out = LN(a + b) * g + beta ----------------
__global__ __launch_bounds__(256)
void ln_kernel(const float* __restrict__ a, const float* __restrict__ b,
               const float* __restrict__ g, const float* __restrict__ beta,
               float* __restrict__ out)
{
    int row  = blockIdx.x*8 + (threadIdx.x >> 5);
    int lane = threadIdx.x & 31;
    const float* pa = a + (size_t)row*DM;
    const float* pb = b + (size_t)row*DM;
    float v[16];
    float s = 0.f, s2 = 0.f;
#pragma unroll
    for (int i = 0; i < 16; i++) {
        int cix = lane + i*32;
        float x = pa[cix] + pb[cix];
        v[i] = x; s += x; s2 = fmaf(x, x, s2);
    }
#pragma unroll
    for (int off = 16; off > 0; off >>= 1) {
        s  += __shfl_xor_sync(0xffffffffu, s,  off);
        s2 += __shfl_xor_sync(0xffffffffu, s2, off);
    }
    float mean = s * (1.f/DM);
    float var  = s2 * (1.f/DM) - mean*mean;
    float inv  = rsqrtf(var + 1e-5f);
    float* po = out + (size_t)row*DM;
#pragma unroll
    for (int i = 0; i < 16; i++) {
        int cix = lane + i*32;
        po[cix] = (v[i]-mean)*inv*g[cix] + beta[cix];
    }
}

// ---------------- launch ----------------
extern "C" void kernel_launch(void* const* d_in, const int* in_sizes, int n_in,
                              void* d_out, int out_size)
{
    const float* x       = (const float*)d_in[0];
    const float* in1_w   = (const float*)d_in[1];
    const float* conv1_w = (const float*)d_in[2];
    const float* conv1_b = (const float*)d_in[3];
    const float* xp1_w   = (const float*)d_in[4];
    const float* dtp1_w  = (const float*)d_in[5];
    const float* dtp1_b  = (const float*)d_in[6];
    const float* Alog1   = (const float*)d_in[7];
    const float* D1      = (const float*)d_in[8];
    const float* outp1_w = (const float*)d_in[9];
    const float* in2_w   = (const float*)d_in[10];
    const float* conv2_w = (const float*)d_in[11];
    const float* conv2_b = (const float*)d_in[12];
    const float* xp2_w   = (const float*)d_in[13];
    const float* dtp2_w  = (const float*)d_in[14];
    const float* dtp2_b  = (const float*)d_in[15];
    const float* Alog2   = (const float*)d_in[16];
    const float* D2      = (const float*)d_in[17];
    const float* outp2_w = (const float*)d_in[18];
    const float* c1_w    = (const float*)d_in[19];
    const float* c1_b    = (const float*)d_in[20];
    const float* c2_w    = (const float*)d_in[21];
    const float* c2_b    = (const float*)d_in[22];
    const float* ln1_g   = (const float*)d_in[23];
    const float* ln1_b   = (const float*)d_in[24];
    const float* ln2_g   = (const float*)d_in[25];
    const float* ln2_b   = (const float*)d_in[26];
    float* out = (float*)d_out;

    float *xz1,*xz2,*xc1,*xc2,*xdbl1,*xdbl2,*yb,*o,*xln,*hff,*yff;
    cudaGetSymbolAddress((void**)&xz1,  g_xz1);
    cudaGetSymbolAddress((void**)&xz2,  g_xz2);
    cudaGetSymbolAddress((void**)&xc1,  g_xc1);
    cudaGetSymbolAddress((void**)&xc2,  g_xc2);
    cudaGetSymbolAddress((void**)&xdbl1,g_xdbl1);
    cudaGetSymbolAddress((void**)&xdbl2,g_xdbl2);
    cudaGetSymbolAddress((void**)&yb,   g_y);
    cudaGetSymbolAddress((void**)&o,    g_o);
    cudaGetSymbolAddress((void**)&xln,  g_xln);
    cudaGetSymbolAddress((void**)&hff,  g_hff);
    cudaGetSymbolAddress((void**)&yff,  g_yff);

    prep_kernel<<<128,256>>>(Alog1, Alog2, dtp1_w, dtp2_w);

    // in_proj, both dirs: (8192x2048) = x @ W^T, K=512
    {
        dim3 g(2*DIN/128, MROWS/128);
        tgemm<128,0><<<g,256>>>(x, DM, in1_w, in1_w, DM, DM, xz1, 2*DIN, DM, nullptr);
        tgemm<128,0><<<g,256>>>(x, DM, in2_w, in2_w, DM, DM, xz2, 2*DIN, DM, nullptr);
    }

    // depthwise conv + silu
    {
        dim3 g(MROWS*DIN/256, 2);
        conv_kernel<<<g,256>>>(conv1_w, conv1_b, conv2_w, conv2_b);
    }

    // x_proj: (8192x64) = xc @ xp_w^T, K=1024
    {
        dim3 g(1, MROWS/128);
        tgemm<64,0><<<g,128>>>(xc1, DIN, xp1_w, xp1_w, DIN, DIN, xdbl1, 64, DIN, nullptr);
        tgemm<64,0><<<g,128>>>(xc2, DIN, xp2_w, xp2_w, DIN, DIN, xdbl2, 64, DIN, nullptr);
    }

    // dt_proj + softplus
    {
        dim3 g(MROWS, 2);
        dt_kernel<<<g,256>>>(dtp1_b, dtp2_b);
    }

    // selective scan + gate (dir1 backwards, already un-flipped on store)
    {
        dim3 gs(Bq*DIN/64, 2);
        scan_kernel<<<gs,256>>>(D1, D2);
    }

    // out_proj fused: o = [y1|y2](8192x2048) @ [out1^T;out2^T], K=2048 split at 1024
    {
        dim3 g(DM/128, MROWS/128);
        tgemm<128,0><<<g,256>>>(yb, 2*DIN, outp1_w, outp2_w, DIN, DIN, o, DM, 2*DIN, nullptr);
    }

    // LN1: xln = LN(o + x)
    ln_kernel<<<MROWS/8,256>>>(o, x, ln1_g, ln1_b, xln);

    // FFN
    {
        dim3 g1(DFF/128, MROWS/128);
        tgemm<128,2><<<g1,256>>>(xln, DM, c1_w, c1_w, DM, DM, hff, DFF, DM, c1_b);
        dim3 g2(DM/128, MROWS/128);
        tgemm<128,3><<<g2,256>>>(hff, DFF, c2_w, c2_w, DFF, DFF, yff, DM, DFF, c2_b);
    }

    // LN2: out = LN(xln + yff)
    ln_kernel<<<MROWS/8,256>>>(xln, yff, ln2_g, ln2_b, out);
}

// round 4
// speedup vs baseline: 1.8215x; 1.1499x over previous
#include <cuda_runtime.h>
#include <cuda_bf16.h>
#include <math.h>
#include <stdint.h>

#define Bq   8
#define Lq   1024
#define DM   512
#define DIN  1024
#define DFF  2048
#define DS   16
#define DTR  32
#define MROWS (Bq*Lq)   /* 8192 token rows */

typedef __nv_bfloat16 bf16;

// ---------------- fp32 scratch ----------------
__device__ float g_xz1 [MROWS*2*DIN];
__device__ float g_xz2 [MROWS*2*DIN];
__device__ float g_xc1 [MROWS*DIN];
__device__ float g_xc2 [MROWS*DIN];
__device__ float g_xdbl1[MROWS*64];
__device__ float g_xdbl2[MROWS*64];
__device__ float g_dt1 [MROWS*DIN];
__device__ float g_dt2 [MROWS*DIN];
__device__ float g_o   [MROWS*DM];
__device__ float g_xln [MROWS*DM];
__device__ float g_yff [MROWS*DM];
__device__ float g_A   [2*DIN*DS];
__device__ float g_Wt  [2*DTR*DIN];

// ---------------- bf16 hi/lo split activations ----------------
__device__ bf16 g_xh  [MROWS*DM],    g_xl  [MROWS*DM];
__device__ bf16 g_xc1h[MROWS*DIN],   g_xc1l[MROWS*DIN];
__device__ bf16 g_xc2h[MROWS*DIN],   g_xc2l[MROWS*DIN];
__device__ bf16 g_yh  [MROWS*2*DIN], g_yl  [MROWS*2*DIN];
__device__ bf16 g_xlnh[MROWS*DM],    g_xlnl[MROWS*DM];
__device__ bf16 g_hffh[MROWS*DFF],   g_hffl[MROWS*DFF];

// ---------------- bf16 hi/lo split weights ----------------
__device__ bf16 g_win1h[2*DIN*DM], g_win1l[2*DIN*DM];
__device__ bf16 g_win2h[2*DIN*DM], g_win2l[2*DIN*DM];
__device__ bf16 g_wxp1h[64*DIN],   g_wxp1l[64*DIN];
__device__ bf16 g_wxp2h[64*DIN],   g_wxp2l[64*DIN];
__device__ bf16 g_woh  [DM*2*DIN], g_wol  [DM*2*DIN];   // fused [out1|out2]
__device__ bf16 g_wc1h [DFF*DM],   g_wc1l [DFF*DM];
__device__ bf16 g_wc2h [DM*DFF],   g_wc2l [DM*DFF];

// ======================= helpers =======================
__device__ __forceinline__ uint32_t smem_u32(const void* p) {
    uint32_t a;
    asm("{ .reg .u64 t; cvta.to.shared.u64 t, %1; cvt.u32.u64 %0, t; }" : "=r"(a) : "l"(p));
    return a;
}
__device__ __forceinline__ void ldmx4(uint32_t* r, uint32_t addr) {
    asm volatile("ldmatrix.sync.aligned.m8n8.x4.shared.b16 {%0,%1,%2,%3}, [%4];"
                 : "=r"(r[0]), "=r"(r[1]), "=r"(r[2]), "=r"(r[3]) : "r"(addr));
}
__device__ __forceinline__ void ldmx2(uint32_t* r, uint32_t addr) {
    asm volatile("ldmatrix.sync.aligned.m8n8.x2.shared.b16 {%0,%1}, [%2];"
                 : "=r"(r[0]), "=r"(r[1]) : "r"(addr));
}
__device__ __forceinline__ void hmma(float* d, const uint32_t* a, const uint32_t* b) {
    asm volatile(
        "mma.sync.aligned.m16n8k16.row.col.f32.bf16.bf16.f32 "
        "{%0,%1,%2,%3}, {%4,%5,%6,%7}, {%8,%9}, {%0,%1,%2,%3};"
        : "+f"(d[0]), "+f"(d[1]), "+f"(d[2]), "+f"(d[3])
        : "r"(a[0]), "r"(a[1]), "r"(a[2]), "r"(a[3]), "r"(b[0]), "r"(b[1]));
}
__device__ __forceinline__ void cpa16(uint32_t dst, const void* src) {
    asm volatile("cp.async.cg.shared.global [%0], [%1], 16;" :: "r"(dst), "l"(src));
}
#define CP_COMMIT() asm volatile("cp.async.commit_group;" ::: "memory")
template<int N> __device__ __forceinline__ void cp_wait() {
    asm volatile("cp.async.wait_group %0;" :: "n"(N) : "memory");
}
__device__ __forceinline__ float gelu_exact(float x) {
    return 0.5f * x * (1.0f + erff(x * 0.70710678118654752f));
}
__device__ __forceinline__ void split1(float v, bf16& h, bf16& l) {
    h = __float2bfloat16_rn(v);
    l = __float2bfloat16_rn(v - __bfloat162float(h));
}

// ======================= HMMA bf16 split GEMM (pre-split operands) =======================
// C[m,n] = sum_k A[m,k]*B[n,k]; A,B given as bf16 hi/lo pairs.
// Block tile 128 x BN, BK=32, 2-stage cp.async pipeline. Warp tile 64x32.
// EPI: 0 = fp32 store, 3 = bias fp32 store, 4 = bias+GELU, split bf16 store.
template<int BN, int EPI>
__global__ __launch_bounds__(64*(BN/32))
void tgemm(const bf16* __restrict__ Ah_, const bf16* __restrict__ Al_, int lda,
           const bf16* __restrict__ Bh_, const bf16* __restrict__ Bl_, int ldb,
           float* __restrict__ C, bf16* __restrict__ Ch, bf16* __restrict__ Cl,
           int ldc, int K, const float* __restrict__ bias)
{
    constexpr int WN = BN / 32;
    constexpr int T  = 64 * WN;
    constexpr int PK = 40;                    // padded k stride (elems), 80B
    constexpr int ASZ = 128 * PK * 2;         // bytes per half
    constexpr int BSZ = BN  * PK * 2;

    extern __shared__ char smem[];
    const uint32_t base = smem_u32(smem);
    const uint32_t aS0 = base,              aS1 = base + 2*ASZ;
    const uint32_t bS0 = base + 4*ASZ,      bS1 = base + 4*ASZ + 2*BSZ;

    const int tid  = threadIdx.x;
    const int wid  = tid >> 5, lane = tid & 31;
    const int warp_m = wid & 1, warp_n = wid >> 1;
    const int m0 = blockIdx.y * 128;
    const int n0 = blockIdx.x * BN;

    float acc[4][4][4];
#pragma unroll
    for (int i = 0; i < 4; i++)
#pragma unroll
        for (int j = 0; j < 4; j++)
#pragma unroll
            for (int q = 0; q < 4; q++) acc[i][j][q] = 0.f;

    // ldmatrix per-thread offsets
    const int rA = (lane & 15);
    const int cA = (lane >> 4) * 8;
    const int l2 = lane & 15;
    const int rB = l2 & 7;
    const int cB = (l2 >> 3) * 8;

    auto load_tiles = [&](int k0, uint32_t aS, uint32_t bS) {
        // A: 128 rows x 32 k x 2 halves = 1024 16B chunks
#pragma unroll
        for (int m = 0; m < 1024 / T; m++) {
            int cid = tid + m * T;
            int half = cid >> 9, rem = cid & 511;
            int row = rem >> 2, c4 = rem & 3;
            const bf16* src = (half ? Al_ : Ah_) + (size_t)(m0 + row) * lda + k0 + c4 * 8;
            cpa16(aS + half * ASZ + (row * PK + c4 * 8) * 2, src);
        }
        constexpr int BCH = BN * 8;
#pragma unroll
        for (int m = 0; m < BCH / T; m++) {
            int cid = tid + m * T;
            int half = cid / (BCH / 2), rem = cid % (BCH / 2);
            int row = rem >> 2, c4 = rem & 3;
            const bf16* src = (half ? Bl_ : Bh_) + (size_t)(n0 + row) * ldb + k0 + c4 * 8;
            cpa16(bS + half * BSZ + (row * PK + c4 * 8) * 2, src);
        }
    };

    const int nk = K / 32;
    load_tiles(0, aS0, bS0);
    CP_COMMIT();

    for (int i = 0; i < nk; i++) {
        if (i + 1 < nk) {
            load_tiles((i + 1) * 32, (i & 1) ? aS0 : aS1, (i & 1) ? bS0 : bS1);
            CP_COMMIT();
            cp_wait<1>();
        } else {
            CP_COMMIT();           // empty group keeps wait-count logic uniform
            cp_wait<0>();
        }
        __syncthreads();

        const uint32_t aHi = (i & 1) ? aS1 : aS0;
        const uint32_t bHi = (i & 1) ? bS1 : bS0;
        const uint32_t aLo = aHi + ASZ, bLo = bHi + BSZ;

#pragma unroll
        for (int kk = 0; kk < 32; kk += 16) {
            uint32_t Ahr[4][4], Bhr[4][2];
            const int aoff = kk + cA;
            const int boff = kk + cB;
#pragma unroll
            for (int mf = 0; mf < 4; mf++)
                ldmx4(Ahr[mf], aHi + ((warp_m*64 + mf*16 + rA) * PK + aoff) * 2);
#pragma unroll
            for (int nf = 0; nf < 4; nf++)
                ldmx2(Bhr[nf], bHi + ((warp_n*32 + nf*8 + rB) * PK + boff) * 2);
#pragma unroll
            for (int mf = 0; mf < 4; mf++)
#pragma unroll
                for (int nf = 0; nf < 4; nf++)
                    hmma(acc[mf][nf], Ahr[mf], Bhr[nf]);

            uint32_t Blr[4][2];
#pragma unroll
            for (int nf = 0; nf < 4; nf++)
                ldmx2(Blr[nf], bLo + ((warp_n*32 + nf*8 + rB) * PK + boff) * 2);
#pragma unroll
            for (int mf = 0; mf < 4; mf++)
#pragma unroll
                for (int nf = 0; nf < 4; nf++)
                    hmma(acc[mf][nf], Ahr[mf], Blr[nf]);

            uint32_t Alr[4][4];
#pragma unroll
            for (int mf = 0; mf < 4; mf++)
                ldmx4(Alr[mf], aLo + ((warp_m*64 + mf*16 + rA) * PK + aoff) * 2);
#pragma unroll
            for (int mf = 0; mf < 4; mf++)
#pragma unroll
                for (int nf = 0; nf < 4; nf++)
                    hmma(acc[mf][nf], Alr[mf], Bhr[nf]);
        }
        __syncthreads();
    }

    // ---- epilogue ----
    const int rr = lane >> 2;
    const int cc = (lane & 3) * 2;
#pragma unroll
    for (int mf = 0; mf < 4; mf++) {
#pragma unroll
        for (int nf = 0; nf < 4; nf++) {
            int col = n0 + warp_n*32 + nf*8 + cc;
            float b0 = 0.f, b1 = 0.f;
            if (EPI == 3 || EPI == 4) { b0 = bias[col]; b1 = bias[col+1]; }
#pragma unroll
            for (int h = 0; h < 2; h++) {
                int row = m0 + warp_m*64 + mf*16 + rr + h*8;
                float v0 = acc[mf][nf][h*2+0];
                float v1 = acc[mf][nf][h*2+1];
                if (EPI == 3) {
                    v0 += b0; v1 += b1;
                    *reinterpret_cast<float2*>(C + (size_t)row * ldc + col) = make_float2(v0, v1);
                } else if (EPI == 4) {
                    v0 = gelu_exact(v0 + b0); v1 = gelu_exact(v1 + b1);
                    bf16 h0, l0, h1, l1;
                    split1(v0, h0, l0); split1(v1, h1, l1);
                    __nv_bfloat162 ph = __nv_bfloat162(h0, h1);
                    __nv_bfloat162 pl = __nv_bfloat162(l0, l1);
                    *reinterpret_cast<__nv_bfloat162*>(Ch + (size_t)row * ldc + col) = ph;
                    *reinterpret_cast<__nv_bfloat162*>(Cl + (size_t)row * ldc + col) = pl;
                } else {
                    *reinterpret_cast<float2*>(C + (size_t)row * ldc + col) = make_float2(v0, v1);
                }
            }
        }
    }
}

// ---------------- generic fp32 -> bf16 hi/lo split (strided dst) ----------------
__global__ void wsplit(const float* __restrict__ s, bf16* __restrict__ h, bf16* __restrict__ l,
                       int n, int Ksrc, int dstStride, int dstOff)
{
    int i = blockIdx.x*256 + threadIdx.x;
    if (i >= n) return;
    int r = i / Ksrc, k = i - r*Ksrc;
    float v = s[i];
    bf16 hv, lv;
    split1(v, hv, lv);
    size_t d = (size_t)r*dstStride + dstOff + k;
    h[d] = hv; l[d] = lv;
}

// ---------------- prep: A = -exp(Alog); transpose dt_proj weights ----------------
__global__ void prep_kernel(const float* __restrict__ Alog1, const float* __restrict__ Alog2,
                            const float* __restrict__ Wdt1,  const float* __restrict__ Wdt2)
{
    int i = blockIdx.x*256 + threadIdx.x;
    if (i < DIN*DS) {
        g_A[i]          = -__expf(Alog1[i]);
        g_A[DIN*DS + i] = -__expf(Alog2[i]);
    }
    if (i < DIN*DTR) {
        int d = i >> 5, k = i & 31;
        g_Wt[k*DIN + d]           = Wdt1[i];
        g_Wt[DTR*DIN + k*DIN + d] = Wdt2[i];
    }
}

// ---------------- depthwise causal conv (k=4) + bias + SiLU, dual output ----------------
__global__ __launch_bounds__(256)
void conv_kernel(const float* __restrict__ w1, const float* __restrict__ b1,
                 const float* __restrict__ w2, const float* __restrict__ b2)
{
    int dir = blockIdx.y;
    const float* xz = dir ? g_xz2 : g_xz1;
    const float* w  = dir ? w2 : w1;
    const float* cb = dir ? b2 : b1;
    float* xc       = dir ? g_xc2 : g_xc1;
    bf16* xch       = dir ? g_xc2h : g_xc1h;
    bf16* xcl       = dir ? g_xc2l : g_xc1l;

    int idx = blockIdx.x*256 + threadIdx.x;
    int d   = idx & (DIN-1);
    int row = idx >> 10;
    int t   = row & (Lq-1);
    float w0=w[d*4+0], w1_=w[d*4+1], w2_=w[d*4+2], w3=w[d*4+3];
    float s = cb[d];
    const float* base = xz + (size_t)row*(2*DIN) + d;
    if (dir == 0) {
        s += w3 * base[0];
        if (t >= 1) s += w2_ * base[-1*(2*DIN)];
        if (t >= 2) s += w1_ * base[-2*(2*DIN)];
        if (t >= 3) s += w0  * base[-3*(2*DIN)];
    } else {
        s += w3 * base[0];
        if (t <= Lq-2) s += w2_ * base[ 1*(2*DIN)];
        if (t <= Lq-3) s += w1_ * base[ 2*(2*DIN)];
        if (t <= Lq-4) s += w0  * base[ 3*(2*DIN)];
    }
    float r = s / (1.f + __expf(-s));
    size_t o = (size_t)row*DIN + d;
    xc[o] = r;
    bf16 hv, lv; split1(r, hv, lv);
    xch[o] = hv; xcl[o] = lv;
}

// ---------------- dt = softplus(dt_raw @ dtp_w^T + b) ----------------
__global__ __launch_bounds__(256)
void dt_kernel(const float* __restrict__ b1, const float* __restrict__ b2)
{
    int dir = blockIdx.y;
    const float* xdbl = dir ? g_xdbl2 : g_xdbl1;
    const float* Wt   = g_Wt + dir*DTR*DIN;
    const float* bias = dir ? b2 : b1;
    float* out        = dir ? g_dt2 : g_dt1;

    __shared__ float r[DTR];
    int row = blockIdx.x;
    if (threadIdx.x < DTR) r[threadIdx.x] = xdbl[(size_t)row*64 + threadIdx.x];
    __syncthreads();
#pragma unroll
    for (int q = 0; q < 4; q++) {
        int d = threadIdx.x + q*256;
        float s = bias[d];
#pragma unroll
        for (int k = 0; k < DTR; k++) s = fmaf(r[k], Wt[k*DIN + d], s);
        float sp = (s > 20.f) ? s : log1pf(__expf(s));
        out[(size_t)row*DIN + d] = sp;
    }
}

// ---------------- selective scan + D-skip + SiLU(z) gate -> bf16 hi/lo ----------------
__global__ __launch_bounds__(256)
void scan_kernel(const float* __restrict__ D1, const float* __restrict__ D2)
{
    int dir = blockIdx.y;
    const float* dt   = dir ? g_dt2  : g_dt1;
    const float* xc   = dir ? g_xc2  : g_xc1;
    const float* xdbl = dir ? g_xdbl2: g_xdbl1;
    const float* xz   = dir ? g_xz2  : g_xz1;
    const float* Aexp = g_A + dir*DIN*DS;
    const float* Dv_  = dir ? D2 : D1;

    int warp = threadIdx.x >> 5, lane = threadIdx.x & 31;
    int sg = lane & 3;
    int c  = blockIdx.x*64 + warp*8 + (lane >> 2);
    int b  = c >> 10, d = c & (DIN-1);

    const float4 a4 = *(const float4*)(Aexp + d*DS + sg*4);
    const float Dd = Dv_[d];
    float h0=0.f, h1=0.f, h2=0.f, h3=0.f;
    const int rbase = b*Lq;

    for (int i = 0; i < Lq; i++) {
        int t = dir ? (Lq-1-i) : i;
        size_t row = rbase + t;
        float dtv = dt[row*DIN + d];
        float uv  = xc[row*DIN + d];
        const float4 Bv = *(const float4*)(xdbl + row*64 + DTR + sg*4);
        const float4 Cv = *(const float4*)(xdbl + row*64 + DTR + DS + sg*4);
        float du = dtv*uv;
        h0 = fmaf(__expf(dtv*a4.x), h0, du*Bv.x);
        h1 = fmaf(__expf(dtv*a4.y), h1, du*Bv.y);
        h2 = fmaf(__expf(dtv*a4.z), h2, du*Bv.z);
        h3 = fmaf(__expf(dtv*a4.w), h3, du*Bv.w);
        float p = h0*Cv.x + h1*Cv.y + h2*Cv.z + h3*Cv.w;
        p += __shfl_xor_sync(0xffffffffu, p, 1);
        p += __shfl_xor_sync(0xffffffffu, p, 2);
        if (sg == 0) {
            float zv = xz[row*(2*DIN) + DIN + d];
            float yv = (p + uv*Dd) * (zv / (1.f + __expf(-zv)));
            size_t o = row*(2*DIN) + dir*DIN + d;
            bf16 hv, lv; split1(yv, hv, lv);
            g_yh[o] = hv; g_yl[o] = lv;
        }
    }
}

// ---------------- LayerNorm: out = LN(a + b) * g + beta (+ optional bf16 split) --------
__global__ __launch_bounds__(256)
void ln_kernel(const float* __restrict__ a, const float* __restrict__ b,
               const float* __restrict__ g, const float* __restrict__ beta,
               float* __restrict__ out, bf16* __restrict__ oh, bf16* __restrict__ ol)
{
    int row  = blockIdx.x*8 + (threadIdx.x >> 5);
    int lane = threadIdx.x & 31;
    const float* pa = a + (size_t)row*DM;
    const float* pb = b + (size_t)row*DM;
    float v[16];
    float s = 0.f, s2 = 0.f;
#pragma unroll
    for (int i = 0; i < 16; i++) {
        int cix = lane + i*32;
        float x = pa[cix] + pb[cix];
        v[i] = x; s += x; s2 = fmaf(x, x, s2);
    }
#pragma unroll
    for (int off = 16; off > 0; off >>= 1) {
        s  += __shfl_xor_sync(0xffffffffu, s,  off);
        s2 += __shfl_xor_sync(0xffffffffu, s2, off);
    }
    float mean = s * (1.f/DM);
    float var  = s2 * (1.f/DM) - mean*mean;
    float inv  = rsqrtf(var + 1e-5f);
    float* po = out + (size_t)row*DM;
#pragma unroll
    for (int i = 0; i < 16; i++) {
        int cix = lane + i*32;
        float r = (v[i]-mean)*inv*g[cix] + beta[cix];
        po[cix] = r;
        if (oh) {
            bf16 hv, lv; split1(r, hv, lv);
            oh[(size_t)row*DM + cix] = hv;
            ol[(size_t)row*DM + cix] = lv;
        }
    }
}

// ---------------- launch ----------------
extern "C" void kernel_launch(void* const* d_in, const int* in_sizes, int n_in,
                              void* d_out, int out_size)
{
    const float* x       = (const float*)d_in[0];
    const float* in1_w   = (const float*)d_in[1];
    const float* conv1_w = (const float*)d_in[2];
    const float* conv1_b = (const float*)d_in[3];
    const float* xp1_w   = (const float*)d_in[4];
    const float* dtp1_w  = (const float*)d_in[5];
    const float* dtp1_b  = (const float*)d_in[6];
    const float* Alog1   = (const float*)d_in[7];
    const float* D1      = (const float*)d_in[8];
    const float* outp1_w = (const float*)d_in[9];
    const float* in2_w   = (const float*)d_in[10];
    const float* conv2_w = (const float*)d_in[11];
    const float* conv2_b = (const float*)d_in[12];
    const float* xp2_w   = (const float*)d_in[13];
    const float* dtp2_w  = (const float*)d_in[14];
    const float* dtp2_b  = (const float*)d_in[15];
    const float* Alog2   = (const float*)d_in[16];
    const float* D2      = (const float*)d_in[17];
    const float* outp2_w = (const float*)d_in[18];
    const float* c1_w    = (const float*)d_in[19];
    const float* c1_b    = (const float*)d_in[20];
    const float* c2_w    = (const float*)d_in[21];
    const float* c2_b    = (const float*)d_in[22];
    const float* ln1_g   = (const float*)d_in[23];
    const float* ln1_b   = (const float*)d_in[24];
    const float* ln2_g   = (const float*)d_in[25];
    const float* ln2_b   = (const float*)d_in[26];
    float* out = (float*)d_out;

    float *xz1,*xz2,*xdbl1,*xdbl2,*o,*xln,*yff;
    cudaGetSymbolAddress((void**)&xz1,  g_xz1);
    cudaGetSymbolAddress((void**)&xz2,  g_xz2);
    cudaGetSymbolAddress((void**)&xdbl1,g_xdbl1);
    cudaGetSymbolAddress((void**)&xdbl2,g_xdbl2);
    cudaGetSymbolAddress((void**)&o,    g_o);
    cudaGetSymbolAddress((void**)&xln,  g_xln);
    cudaGetSymbolAddress((void**)&yff,  g_yff);

    bf16 *xh,*xl,*xc1h,*xc1l,*xc2h,*xc2l,*yh,*yl,*xlnh,*xlnl,*hffh,*hffl;
    cudaGetSymbolAddress((void**)&xh,  g_xh);   cudaGetSymbolAddress((void**)&xl,  g_xl);
    cudaGetSymbolAddress((void**)&xc1h,g_xc1h); cudaGetSymbolAddress((void**)&xc1l,g_xc1l);
    cudaGetSymbolAddress((void**)&xc2h,g_xc2h); cudaGetSymbolAddress((void**)&xc2l,g_xc2l);
    cudaGetSymbolAddress((void**)&yh,  g_yh);   cudaGetSymbolAddress((void**)&yl,  g_yl);
    cudaGetSymbolAddress((void**)&xlnh,g_xlnh); cudaGetSymbolAddress((void**)&xlnl,g_xlnl);
    cudaGetSymbolAddress((void**)&hffh,g_hffh); cudaGetSymbolAddress((void**)&hffl,g_hffl);

    bf16 *win1h,*win1l,*win2h,*win2l,*wxp1h,*wxp1l,*wxp2h,*wxp2l,*woh,*wol,*wc1h,*wc1l,*wc2h,*wc2l;
    cudaGetSymbolAddress((void**)&win1h,g_win1h); cudaGetSymbolAddress((void**)&win1l,g_win1l);
    cudaGetSymbolAddress((void**)&win2h,g_win2h); cudaGetSymbolAddress((void**)&win2l,g_win2l);
    cudaGetSymbolAddress((void**)&wxp1h,g_wxp1h); cudaGetSymbolAddress((void**)&wxp1l,g_wxp1l);
    cudaGetSymbolAddress((void**)&wxp2h,g_wxp2h); cudaGetSymbolAddress((void**)&wxp2l,g_wxp2l);
    cudaGetSymbolAddress((void**)&woh,  g_woh);   cudaGetSymbolAddress((void**)&wol,  g_wol);
    cudaGetSymbolAddress((void**)&wc1h, g_wc1h);  cudaGetSymbolAddress((void**)&wc1l, g_wc1l);
    cudaGetSymbolAddress((void**)&wc2h, g_wc2h);  cudaGetSymbolAddress((void**)&wc2l, g_wc2l);

    // dynamic smem sizes
    const int SM128 = 4*(128*40*2) + 4*(128*40*2);  // 81920
    const int SM64  = 4*(128*40*2) + 4*(64*40*2);   // 61440
    cudaFuncSetAttribute(tgemm<128,0>, cudaFuncAttributeMaxDynamicSharedMemorySize, SM128);
    cudaFuncSetAttribute(tgemm<128,3>, cudaFuncAttributeMaxDynamicSharedMemorySize, SM128);
    cudaFuncSetAttribute(tgemm<128,4>, cudaFuncAttributeMaxDynamicSharedMemorySize, SM128);
    cudaFuncSetAttribute(tgemm<64,0>,  cudaFuncAttributeMaxDynamicSharedMemorySize, SM64);

    prep_kernel<<<128,256>>>(Alog1, Alog2, dtp1_w, dtp2_w);

    // weight + input splits
    auto NB = [](int n){ return (n + 255) / 256; };
    wsplit<<<NB(MROWS*DM),256>>>(x, xh, xl, MROWS*DM, DM, DM, 0);
    wsplit<<<NB(2*DIN*DM),256>>>(in1_w, win1h, win1l, 2*DIN*DM, DM, DM, 0);
    wsplit<<<NB(2*DIN*DM),256>>>(in2_w, win2h, win2l, 2*DIN*DM, DM, DM, 0);
    wsplit<<<NB(64*DIN),256>>>(xp1_w, wxp1h, wxp1l, 64*DIN, DIN, DIN, 0);
    wsplit<<<NB(64*DIN),256>>>(xp2_w, wxp2h, wxp2l, 64*DIN, DIN, DIN, 0);
    wsplit<<<NB(DM*DIN),256>>>(outp1_w, woh, wol, DM*DIN, DIN, 2*DIN, 0);
    wsplit<<<NB(DM*DIN),256>>>(outp2_w, woh, wol, DM*DIN, DIN, 2*DIN, DIN);
    wsplit<<<NB(DFF*DM),256>>>(c1_w, wc1h, wc1l, DFF*DM, DM, DM, 0);
    wsplit<<<NB(DM*DFF),256>>>(c2_w, wc2h, wc2l, DM*DFF, DFF, DFF, 0);

    // in_proj, both dirs: (8192x2048) = x @ W^T, K=512
    {
        dim3 g(2*DIN/128, MROWS/128);
        tgemm<128,0><<<g,256,SM128>>>(xh, xl, DM, win1h, win1l, DM, xz1, nullptr, nullptr, 2*DIN, DM, nullptr);
        tgemm<128,0><<<g,256,SM128>>>(xh, xl, DM, win2h, win2l, DM, xz2, nullptr, nullptr, 2*DIN, DM, nullptr);
    }

    // depthwise conv + silu (fp32 + bf16 split outputs)
    {
        dim3 g(MROWS*DIN/256, 2);
        conv_kernel<<<g,256>>>(conv1_w, conv1_b, conv2_w, conv2_b);
    }

    // x_proj: (8192x64) = xc @ xp_w^T, K=1024
    {
        dim3 g(1, MROWS/128);
        tgemm<64,0><<<g,128,SM64>>>(xc1h, xc1l, DIN, wxp1h, wxp1l, DIN, xdbl1, nullptr, nullptr, 64, DIN, nullptr);
        tgemm<64,0><<<g,128,SM64>>>(xc2h, xc2l, DIN, wxp2h, wxp2l, DIN, xdbl2, nullptr, nullptr, 64, DIN, nullptr);
    }

    // dt_proj + softplus
    {
        dim3 g(MROWS, 2);
        dt_kernel<<<g,256>>>(dtp1_b, dtp2_b);
    }

    // selective scan + gate -> bf16 split y
    {
        dim3 gs(Bq*DIN/64, 2);
        scan_kernel<<<gs,256>>>(D1, D2);
    }

    // out_proj fused: o = [y1|y2](8192x2048) @ fused_w^T, K=2048
    {
        dim3 g(DM/128, MROWS/128);
        tgemm<128,0><<<g,256,SM128>>>(yh, yl, 2*DIN, woh, wol, 2*DIN, o, nullptr, nullptr, DM, 2*DIN, nullptr);
    }

    // LN1: xln = LN(o + x)  (+ split)
    ln_kernel<<<MROWS/8,256>>>(o, x, ln1_g, ln1_b, xln, xlnh, xlnl);

    // FFN
    {
        dim3 g1(DFF/128, MROWS/128);
        tgemm<128,4><<<g1,256,SM128>>>(xlnh, xlnl, DM, wc1h, wc1l, DM, nullptr, hffh, hffl, DFF, DM, c1_b);
        dim3 g2(DM/128, MROWS/128);
        tgemm<128,3><<<g2,256,SM128>>>(hffh, hffl, DFF, wc2h, wc2l, DFF, yff, nullptr, nullptr, DM, DFF, c2_b);
    }

    // LN2: out = LN(xln + yff)
    ln_kernel<<<MROWS/8,256>>>(xln, yff, ln2_g, ln2_b, out, nullptr, nullptr);
}

// round 5
// speedup vs baseline: 2.2758x; 1.2494x over previous
#include <cuda_runtime.h>
#include <cuda_fp16.h>
#include <math.h>
#include <stdint.h>

#define Bq   8
#define Lq   1024
#define DM   512
#define DIN  1024
#define DFF  2048
#define DS   16
#define DTR  32
#define MROWS (Bq*Lq)   /* 8192 token rows */

typedef __half h16;

// ---------------- fp32 scratch ----------------
__device__ float g_xz1 [MROWS*2*DIN];
__device__ float g_xz2 [MROWS*2*DIN];
__device__ float g_xc1 [MROWS*DIN];
__device__ float g_xc2 [MROWS*DIN];
__device__ float g_xdbl1[MROWS*64];
__device__ float g_xdbl2[MROWS*64];
__device__ float g_dt1 [MROWS*DIN];
__device__ float g_dt2 [MROWS*DIN];
__device__ float g_o   [MROWS*DM];
__device__ float g_xln [MROWS*DM];
__device__ float g_yff [MROWS*DM];
__device__ float g_A   [2*DIN*DS];
__device__ float g_Wt  [2*DTR*DIN];

// ---------------- fp16 activations ----------------
__device__ h16 g_xh  [MROWS*DM];
__device__ h16 g_xc1h[MROWS*DIN];
__device__ h16 g_xc2h[MROWS*DIN];
__device__ h16 g_yh  [MROWS*2*DIN];    // [dir0 | dir1] per row
__device__ h16 g_xlnh[MROWS*DM];
__device__ h16 g_hffh[MROWS*DFF];

// ---------------- fp16 weights ----------------
__device__ h16 g_win1h[2*DIN*DM];
__device__ h16 g_win2h[2*DIN*DM];
__device__ h16 g_wxp1h[64*DIN];
__device__ h16 g_wxp2h[64*DIN];
__device__ h16 g_woh  [DM*2*DIN];      // fused [out1 | out2]
__device__ h16 g_wc1h [DFF*DM];
__device__ h16 g_wc2h [DM*DFF];

// ======================= helpers =======================
__device__ __forceinline__ uint32_t smem_u32(const void* p) {
    uint32_t a;
    asm("{ .reg .u64 t; cvta.to.shared.u64 t, %1; cvt.u32.u64 %0, t; }" : "=r"(a) : "l"(p));
    return a;
}
__device__ __forceinline__ void ldmx4(uint32_t* r, uint32_t addr) {
    asm volatile("ldmatrix.sync.aligned.m8n8.x4.shared.b16 {%0,%1,%2,%3}, [%4];"
                 : "=r"(r[0]), "=r"(r[1]), "=r"(r[2]), "=r"(r[3]) : "r"(addr));
}
__device__ __forceinline__ void ldmx2(uint32_t* r, uint32_t addr) {
    asm volatile("ldmatrix.sync.aligned.m8n8.x2.shared.b16 {%0,%1}, [%2];"
                 : "=r"(r[0]), "=r"(r[1]) : "r"(addr));
}
__device__ __forceinline__ void hmma(float* d, const uint32_t* a, const uint32_t* b) {
    asm volatile(
        "mma.sync.aligned.m16n8k16.row.col.f32.f16.f16.f32 "
        "{%0,%1,%2,%3}, {%4,%5,%6,%7}, {%8,%9}, {%0,%1,%2,%3};"
        : "+f"(d[0]), "+f"(d[1]), "+f"(d[2]), "+f"(d[3])
        : "r"(a[0]), "r"(a[1]), "r"(a[2]), "r"(a[3]), "r"(b[0]), "r"(b[1]));
}
__device__ __forceinline__ void cpa16(uint32_t dst, const void* src) {
    asm volatile("cp.async.cg.shared.global [%0], [%1], 16;" :: "r"(dst), "l"(src));
}
#define CP_COMMIT() asm volatile("cp.async.commit_group;" ::: "memory")
template<int N> __device__ __forceinline__ void cp_wait() {
    asm volatile("cp.async.wait_group %0;" :: "n"(N) : "memory");
}
__device__ __forceinline__ float gelu_exact(float x) {
    return 0.5f * x * (1.0f + erff(x * 0.70710678118654752f));
}

// ======================= fp16 HMMA GEMM =======================
// C[m,n] = sum_k A[m,k]*B[n,k]; A,B fp16, fp32 accum.
// Block tile 128 x BN, BK=32, 2-stage cp.async pipeline. Warp tile 64x32.
// EPI: 0 = fp32 store, 3 = bias fp32 store, 4 = bias+GELU fp16 store.
template<int BN, int EPI>
__global__ __launch_bounds__(64*(BN/32))
void tgemm(const h16* __restrict__ Ah_, int lda,
           const h16* __restrict__ Bh_, int ldb,
           float* __restrict__ C, h16* __restrict__ Ch,
           int ldc, int K, const float* __restrict__ bias)
{
    constexpr int WN = BN / 32;
    constexpr int T  = 64 * WN;
    constexpr int PK = 40;                    // padded k stride (elems), 80B
    constexpr int ASZ = 128 * PK * 2;         // bytes
    constexpr int BSZ = BN  * PK * 2;

    extern __shared__ char smem[];
    const uint32_t base = smem_u32(smem);

    const int tid  = threadIdx.x;
    const int wid  = tid >> 5, lane = tid & 31;
    const int warp_m = wid & 1, warp_n = wid >> 1;
    const int m0 = blockIdx.y * 128;
    const int n0 = blockIdx.x * BN;

    float acc[4][4][4];
#pragma unroll
    for (int i = 0; i < 4; i++)
#pragma unroll
        for (int j = 0; j < 4; j++)
#pragma unroll
            for (int q = 0; q < 4; q++) acc[i][j][q] = 0.f;

    // ldmatrix per-thread offsets
    const int rA = (lane & 15);
    const int cA = (lane >> 4) * 8;
    const int l2 = lane & 15;
    const int rB = l2 & 7;
    const int cB = (l2 >> 3) * 8;

    auto load_tiles = [&](int k0, uint32_t aS, uint32_t bS) {
        // A: 128 rows x 32 k = 512 16B chunks
#pragma unroll
        for (int m = 0; m < 512 / T; m++) {
            int cid = tid + m * T;
            int row = cid >> 2, c4 = cid & 3;
            const h16* src = Ah_ + (size_t)(m0 + row) * lda + k0 + c4 * 8;
            cpa16(aS + (row * PK + c4 * 8) * 2, src);
        }
        // B: BN rows x 32 k = BN*4 chunks
#pragma unroll
        for (int m = 0; m < (BN * 4) / T; m++) {
            int cid = tid + m * T;
            int row = cid >> 2, c4 = cid & 3;
            const h16* src = Bh_ + (size_t)(n0 + row) * ldb + k0 + c4 * 8;
            cpa16(bS + (row * PK + c4 * 8) * 2, src);
        }
    };

    const int nk = K / 32;
    load_tiles(0, base, base + ASZ);
    CP_COMMIT();

    for (int i = 0; i < nk; i++) {
        if (i + 1 < nk) {
            int s = (i + 1) & 1;
            load_tiles((i + 1) * 32, base + s * (ASZ + BSZ), base + s * (ASZ + BSZ) + ASZ);
            CP_COMMIT();
            cp_wait<1>();
        } else {
            CP_COMMIT();
            cp_wait<0>();
        }
        __syncthreads();

        const uint32_t aS = base + (i & 1) * (ASZ + BSZ);
        const uint32_t bS = aS + ASZ;

#pragma unroll
        for (int kk = 0; kk < 32; kk += 16) {
            uint32_t Ar[4][4], Br[4][2];
            const int aoff = kk + cA;
            const int boff = kk + cB;
#pragma unroll
            for (int mf = 0; mf < 4; mf++)
                ldmx4(Ar[mf], aS + ((warp_m*64 + mf*16 + rA) * PK + aoff) * 2);
#pragma unroll
            for (int nf = 0; nf < 4; nf++)
                ldmx2(Br[nf], bS + ((warp_n*32 + nf*8 + rB) * PK + boff) * 2);
#pragma unroll
            for (int mf = 0; mf < 4; mf++)
#pragma unroll
                for (int nf = 0; nf < 4; nf++)
                    hmma(acc[mf][nf], Ar[mf], Br[nf]);
        }
        __syncthreads();
    }

    // ---- epilogue ----
    const int rr = lane >> 2;
    const int cc = (lane & 3) * 2;
#pragma unroll
    for (int mf = 0; mf < 4; mf++) {
#pragma unroll
        for (int nf = 0; nf < 4; nf++) {
            int col = n0 + warp_n*32 + nf*8 + cc;
            float b0 = 0.f, b1 = 0.f;
            if (EPI == 3 || EPI == 4) { b0 = bias[col]; b1 = bias[col+1]; }
#pragma unroll
            for (int h = 0; h < 2; h++) {
                int row = m0 + warp_m*64 + mf*16 + rr + h*8;
                float v0 = acc[mf][nf][h*2+0];
                float v1 = acc[mf][nf][h*2+1];
                if (EPI == 3) {
                    *reinterpret_cast<float2*>(C + (size_t)row * ldc + col) =
                        make_float2(v0 + b0, v1 + b1);
                } else if (EPI == 4) {
                    v0 = gelu_exact(v0 + b0); v1 = gelu_exact(v1 + b1);
                    __half2 p = __floats2half2_rn(v0, v1);
                    *reinterpret_cast<__half2*>(Ch + (size_t)row * ldc + col) = p;
                } else {
                    *reinterpret_cast<float2*>(C + (size_t)row * ldc + col) =
                        make_float2(v0, v1);
                }
            }
        }
    }
}

// ---------------- fp32 -> fp16 convert (strided dst) ----------------
__global__ void whalf(const float* __restrict__ s, h16* __restrict__ h,
                      int n, int Ksrc, int dstStride, int dstOff)
{
    int i = blockIdx.x*256 + threadIdx.x;
    if (i >= n) return;
    int r = i / Ksrc, k = i - r*Ksrc;
    h[(size_t)r*dstStride + dstOff + k] = __float2half_rn(s[i]);
}

// ---------------- prep: A = -exp(Alog); transpose dt_proj weights ----------------
__global__ void prep_kernel(const float* __restrict__ Alog1, const float* __restrict__ Alog2,
                            const float* __restrict__ Wdt1,  const float* __restrict__ Wdt2)
{
    int i = blockIdx.x*256 + threadIdx.x;
    if (i < DIN*DS) {
        g_A[i]          = -__expf(Alog1[i]);
        g_A[DIN*DS + i] = -__expf(Alog2[i]);
    }
    if (i < DIN*DTR) {
        int d = i >> 5, k = i & 31;
        g_Wt[k*DIN + d]           = Wdt1[i];
        g_Wt[DTR*DIN + k*DIN + d] = Wdt2[i];
    }
}

// ---------------- depthwise causal conv (k=4) + bias + SiLU ----------------
__global__ __launch_bounds__(256)
void conv_kernel(const float* __restrict__ w1, const float* __restrict__ b1,
                 const float* __restrict__ w2, const float* __restrict__ b2)
{
    int dir = blockIdx.y;
    const float* xz = dir ? g_xz2 : g_xz1;
    const float* w  = dir ? w2 : w1;
    const float* cb = dir ? b2 : b1;
    float* xc       = dir ? g_xc2 : g_xc1;
    h16* xch        = dir ? g_xc2h : g_xc1h;

    int idx = blockIdx.x*256 + threadIdx.x;
    int d   = idx & (DIN-1);
    int row = idx >> 10;
    int t   = row & (Lq-1);
    float w0=w[d*4+0], w1_=w[d*4+1], w2_=w[d*4+2], w3=w[d*4+3];
    float s = cb[d];
    const float* base = xz + (size_t)row*(2*DIN) + d;
    if (dir == 0) {
        s += w3 * base[0];
        if (t >= 1) s += w2_ * base[-1*(2*DIN)];
        if (t >= 2) s += w1_ * base[-2*(2*DIN)];
        if (t >= 3) s += w0  * base[-3*(2*DIN)];
    } else {
        s += w3 * base[0];
        if (t <= Lq-2) s += w2_ * base[ 1*(2*DIN)];
        if (t <= Lq-3) s += w1_ * base[ 2*(2*DIN)];
        if (t <= Lq-4) s += w0  * base[ 3*(2*DIN)];
    }
    float r = s / (1.f + __expf(-s));
    size_t o = (size_t)row*DIN + d;
    xc[o] = r;
    xch[o] = __float2half_rn(r);
}

// ---------------- dt = softplus(dt_raw @ dtp_w^T + b) ----------------
__global__ __launch_bounds__(256)
void dt_kernel(const float* __restrict__ b1, const float* __restrict__ b2)
{
    int dir = blockIdx.y;
    const float* xdbl = dir ? g_xdbl2 : g_xdbl1;
    const float* Wt   = g_Wt + dir*DTR*DIN;
    const float* bias = dir ? b2 : b1;
    float* out        = dir ? g_dt2 : g_dt1;

    __shared__ float r[DTR];
    int row = blockIdx.x;
    if (threadIdx.x < DTR) r[threadIdx.x] = xdbl[(size_t)row*64 + threadIdx.x];
    __syncthreads();
#pragma unroll
    for (int q = 0; q < 4; q++) {
        int d = threadIdx.x + q*256;
        float s = bias[d];
#pragma unroll
        for (int k = 0; k < DTR; k++) s = fmaf(r[k], Wt[k*DIN + d], s);
        float sp = (s > 20.f) ? s : log1pf(__expf(s));
        out[(size_t)row*DIN + d] = sp;
    }
}

// ---------------- selective scan + D-skip + SiLU(z) gate -> fp16 ----------------
__global__ __launch_bounds__(256)
void scan_kernel(const float* __restrict__ D1, const float* __restrict__ D2)
{
    int dir = blockIdx.y;
    const float* dt   = dir ? g_dt2  : g_dt1;
    const float* xc   = dir ? g_xc2  : g_xc1;
    const float* xdbl = dir ? g_xdbl2: g_xdbl1;
    const float* xz   = dir ? g_xz2  : g_xz1;
    const float* Aexp = g_A + dir*DIN*DS;
    const float* Dv_  = dir ? D2 : D1;

    int warp = threadIdx.x >> 5, lane = threadIdx.x & 31;
    int sg = lane & 3;
    int c  = blockIdx.x*64 + warp*8 + (lane >> 2);
    int b  = c >> 10, d = c & (DIN-1);

    const float4 a4 = *(const float4*)(Aexp + d*DS + sg*4);
    const float Dd = Dv_[d];
    float h0=0.f, h1=0.f, h2=0.f, h3=0.f;
    const int rbase = b*Lq;

    for (int i = 0; i < Lq; i++) {
        int t = dir ? (Lq-1-i) : i;
        size_t row = rbase + t;
        float dtv = dt[row*DIN + d];
        float uv  = xc[row*DIN + d];
        const float4 Bv = *(const float4*)(xdbl + row*64 + DTR + sg*4);
        const float4 Cv = *(const float4*)(xdbl + row*64 + DTR + DS + sg*4);
        float du = dtv*uv;
        h0 = fmaf(__expf(dtv*a4.x), h0, du*Bv.x);
        h1 = fmaf(__expf(dtv*a4.y), h1, du*Bv.y);
        h2 = fmaf(__expf(dtv*a4.z), h2, du*Bv.z);
        h3 = fmaf(__expf(dtv*a4.w), h3, du*Bv.w);
        float p = h0*Cv.x + h1*Cv.y + h2*Cv.z + h3*Cv.w;
        p += __shfl_xor_sync(0xffffffffu, p, 1);
        p += __shfl_xor_sync(0xffffffffu, p, 2);
        if (sg == 0) {
            float zv = xz[row*(2*DIN) + DIN + d];
            float yv = (p + uv*Dd) * (zv / (1.f + __expf(-zv)));
            g_yh[row*(2*DIN) + dir*DIN + d] = __float2half_rn(yv);
        }
    }
}

// ---------------- LayerNorm: out = LN(a + b) * g + beta (+ optional fp16 copy) ---------
__global__ __launch_bounds__(256)
void ln_kernel(const float* __restrict__ a, const float* __restrict__ b,
               const float* __restrict__ g, const float* __restrict__ beta,
               float* __restrict__ out, h16* __restrict__ oh)
{
    int row  = blockIdx.x*8 + (threadIdx.x >> 5);
    int lane = threadIdx.x & 31;
    const float* pa = a + (size_t)row*DM;
    const float* pb = b + (size_t)row*DM;
    float v[16];
    float s = 0.f, s2 = 0.f;
#pragma unroll
    for (int i = 0; i < 16; i++) {
        int cix = lane + i*32;
        float x = pa[cix] + pb[cix];
        v[i] = x; s += x; s2 = fmaf(x, x, s2);
    }
#pragma unroll
    for (int off = 16; off > 0; off >>= 1) {
        s  += __shfl_xor_sync(0xffffffffu, s,  off);
        s2 += __shfl_xor_sync(0xffffffffu, s2, off);
    }
    float mean = s * (1.f/DM);
    float var  = s2 * (1.f/DM) - mean*mean;
    float inv  = rsqrtf(var + 1e-5f);
    float* po = out + (size_t)row*DM;
#pragma unroll
    for (int i = 0; i < 16; i++) {
        int cix = lane + i*32;
        float r = (v[i]-mean)*inv*g[cix] + beta[cix];
        po[cix] = r;
        if (oh) oh[(size_t)row*DM + cix] = __float2half_rn(r);
    }
}

// ---------------- launch ----------------
extern "C" void kernel_launch(void* const* d_in, const int* in_sizes, int n_in,
                              void* d_out, int out_size)
{
    const float* x       = (const float*)d_in[0];
    const float* in1_w   = (const float*)d_in[1];
    const float* conv1_w = (const float*)d_in[2];
    const float* conv1_b = (const float*)d_in[3];
    const float* xp1_w   = (const float*)d_in[4];
    const float* dtp1_w  = (const float*)d_in[5];
    const float* dtp1_b  = (const float*)d_in[6];
    const float* Alog1   = (const float*)d_in[7];
    const float* D1      = (const float*)d_in[8];
    const float* outp1_w = (const float*)d_in[9];
    const float* in2_w   = (const float*)d_in[10];
    const float* conv2_w = (const float*)d_in[11];
    const float* conv2_b = (const float*)d_in[12];
    const float* xp2_w   = (const float*)d_in[13];
    const float* dtp2_w  = (const float*)d_in[14];
    const float* dtp2_b  = (const float*)d_in[15];
    const float* Alog2   = (const float*)d_in[16];
    const float* D2      = (const float*)d_in[17];
    const float* outp2_w = (const float*)d_in[18];
    const float* c1_w    = (const float*)d_in[19];
    const float* c1_b    = (const float*)d_in[20];
    const float* c2_w    = (const float*)d_in[21];
    const float* c2_b    = (const float*)d_in[22];
    const float* ln1_g   = (const float*)d_in[23];
    const float* ln1_b   = (const float*)d_in[24];
    const float* ln2_g   = (const float*)d_in[25];
    const float* ln2_b   = (const float*)d_in[26];
    float* out = (float*)d_out;

    float *xz1,*xz2,*xdbl1,*xdbl2,*o,*xln,*yff;
    cudaGetSymbolAddress((void**)&xz1,  g_xz1);
    cudaGetSymbolAddress((void**)&xz2,  g_xz2);
    cudaGetSymbolAddress((void**)&xdbl1,g_xdbl1);
    cudaGetSymbolAddress((void**)&xdbl2,g_xdbl2);
    cudaGetSymbolAddress((void**)&o,    g_o);
    cudaGetSymbolAddress((void**)&xln,  g_xln);
    cudaGetSymbolAddress((void**)&yff,  g_yff);

    h16 *xh,*xc1h,*xc2h,*yh,*xlnh,*hffh;
    cudaGetSymbolAddress((void**)&xh,  g_xh);
    cudaGetSymbolAddress((void**)&xc1h,g_xc1h);
    cudaGetSymbolAddress((void**)&xc2h,g_xc2h);
    cudaGetSymbolAddress((void**)&yh,  g_yh);
    cudaGetSymbolAddress((void**)&xlnh,g_xlnh);
    cudaGetSymbolAddress((void**)&hffh,g_hffh);

    h16 *win1h,*win2h,*wxp1h,*wxp2h,*woh,*wc1h,*wc2h;
    cudaGetSymbolAddress((void**)&win1h,g_win1h);
    cudaGetSymbolAddress((void**)&win2h,g_win2h);
    cudaGetSymbolAddress((void**)&wxp1h,g_wxp1h);
    cudaGetSymbolAddress((void**)&wxp2h,g_wxp2h);
    cudaGetSymbolAddress((void**)&woh,  g_woh);
    cudaGetSymbolAddress((void**)&wc1h, g_wc1h);
    cudaGetSymbolAddress((void**)&wc2h, g_wc2h);

    // dyn smem: 2 stages x (A 128*40*2 + B BN*40*2)
    const int SM128 = 2*(10240 + 10240);  // 40960
    const int SM64  = 2*(10240 + 5120);   // 30720
    cudaFuncSetAttribute(tgemm<128,0>, cudaFuncAttributeMaxDynamicSharedMemorySize, SM128);
    cudaFuncSetAttribute(tgemm<128,3>, cudaFuncAttributeMaxDynamicSharedMemorySize, SM128);
    cudaFuncSetAttribute(tgemm<128,4>, cudaFuncAttributeMaxDynamicSharedMemorySize, SM128);
    cudaFuncSetAttribute(tgemm<64,0>,  cudaFuncAttributeMaxDynamicSharedMemorySize, SM64);

    prep_kernel<<<128,256>>>(Alog1, Alog2, dtp1_w, dtp2_w);

    auto NB = [](int n){ return (n + 255) / 256; };
    whalf<<<NB(MROWS*DM),256>>>(x, xh, MROWS*DM, DM, DM, 0);
    whalf<<<NB(2*DIN*DM),256>>>(in1_w, win1h, 2*DIN*DM, DM, DM, 0);
    whalf<<<NB(2*DIN*DM),256>>>(in2_w, win2h, 2*DIN*DM, DM, DM, 0);
    whalf<<<NB(64*DIN),256>>>(xp1_w, wxp1h, 64*DIN, DIN, DIN, 0);
    whalf<<<NB(64*DIN),256>>>(xp2_w, wxp2h, 64*DIN, DIN, DIN, 0);
    whalf<<<NB(DM*DIN),256>>>(outp1_w, woh, DM*DIN, DIN, 2*DIN, 0);
    whalf<<<NB(DM*DIN),256>>>(outp2_w, woh, DM*DIN, DIN, 2*DIN, DIN);
    whalf<<<NB(DFF*DM),256>>>(c1_w, wc1h, DFF*DM, DM, DM, 0);
    whalf<<<NB(DM*DFF),256>>>(c2_w, wc2h, DM*DFF, DFF, DFF, 0);

    // in_proj, both dirs: (8192x2048) = x @ W^T, K=512
    {
        dim3 g(2*DIN/128, MROWS/128);
        tgemm<128,0><<<g,256,SM128>>>(xh, DM, win1h, DM, xz1, nullptr, 2*DIN, DM, nullptr);
        tgemm<128,0><<<g,256,SM128>>>(xh, DM, win2h, DM, xz2, nullptr, 2*DIN, DM, nullptr);
    }

    // depthwise conv + silu
    {
        dim3 g(MROWS*DIN/256, 2);
        conv_kernel<<<g,256>>>(conv1_w, conv1_b, conv2_w, conv2_b);
    }

    // x_proj: (8192x64) = xc @ xp_w^T, K=1024
    {
        dim3 g(1, MROWS/128);
        tgemm<64,0><<<g,128,SM64>>>(xc1h, DIN, wxp1h, DIN, xdbl1, nullptr, 64, DIN, nullptr);
        tgemm<64,0><<<g,128,SM64>>>(xc2h, DIN, wxp2h, DIN, xdbl2, nullptr, 64, DIN, nullptr);
    }

    // dt_proj + softplus
    {
        dim3 g(MROWS, 2);
        dt_kernel<<<g,256>>>(dtp1_b, dtp2_b);
    }

    // selective scan + gate -> fp16 y
    {
        dim3 gs(Bq*DIN/64, 2);
        scan_kernel<<<gs,256>>>(D1, D2);
    }

    // out_proj fused: o = [y1|y2](8192x2048) @ fused_w^T, K=2048
    {
        dim3 g(DM/128, MROWS/128);
        tgemm<128,0><<<g,256,SM128>>>(yh, 2*DIN, woh, 2*DIN, o, nullptr, DM, 2*DIN, nullptr);
    }

    // LN1: xln = LN(o + x)  (+ fp16 copy)
    ln_kernel<<<MROWS/8,256>>>(o, x, ln1_g, ln1_b, xln, xlnh);

    // FFN
    {
        dim3 g1(DFF/128, MROWS/128);
        tgemm<128,4><<<g1,256,SM128>>>(xlnh, DM, wc1h, DM, nullptr, hffh, DFF, DM, c1_b);
        dim3 g2(DM/128, MROWS/128);
        tgemm<128,3><<<g2,256,SM128>>>(hffh, DFF, wc2h, DFF, yff, nullptr, DM, DFF, c2_b);
    }

    // LN2: out = LN(xln + yff)
    ln_kernel<<<MROWS/8,256>>>(xln, yff, ln2_g, ln2_b, out, nullptr);
}

// round 6
// speedup vs baseline: 3.8443x; 1.6892x over previous
#include <cuda_runtime.h>
#include <cuda_fp16.h>
#include <math.h>
#include <stdint.h>

#define Bq   8
#define Lq   1024
#define DM   512
#define DIN  1024
#define DFF  2048
#define DS   16
#define DTR  32
#define MROWS (Bq*Lq)   /* 8192 token rows */

typedef __half h16;

// ---------------- fp32 scratch ----------------
__device__ float g_xz1 [MROWS*2*DIN];
__device__ float g_xz2 [MROWS*2*DIN];
__device__ float g_xc1 [MROWS*DIN];
__device__ float g_xc2 [MROWS*DIN];
__device__ float g_xdbl1[MROWS*64];
__device__ float g_xdbl2[MROWS*64];
__device__ float g_dt1 [MROWS*DIN];
__device__ float g_dt2 [MROWS*DIN];
__device__ float g_o   [MROWS*DM];
__device__ float g_xln [MROWS*DM];
__device__ float g_yff [MROWS*DM];
__device__ float g_A   [2*DIN*DS];

// ---------------- fp16 activations ----------------
__device__ h16 g_xh  [MROWS*DM];
__device__ h16 g_xc1h[MROWS*DIN];
__device__ h16 g_xc2h[MROWS*DIN];
__device__ h16 g_yh  [MROWS*2*DIN];    // [dir0 | dir1] per row
__device__ h16 g_xlnh[MROWS*DM];
__device__ h16 g_hffh[MROWS*DFF];

// ---------------- fp16 weights ----------------
__device__ h16 g_win1h[2*DIN*DM];
__device__ h16 g_win2h[2*DIN*DM];
__device__ h16 g_wxp1h[64*DIN];
__device__ h16 g_wxp2h[64*DIN];
__device__ h16 g_woh  [DM*2*DIN];      // fused [out1 | out2]
__device__ h16 g_wc1h [DFF*DM];
__device__ h16 g_wc2h [DM*DFF];

// ======================= helpers =======================
__device__ __forceinline__ uint32_t smem_u32(const void* p) {
    uint32_t a;
    asm("{ .reg .u64 t; cvta.to.shared.u64 t, %1; cvt.u32.u64 %0, t; }" : "=r"(a) : "l"(p));
    return a;
}
__device__ __forceinline__ void ldmx4(uint32_t* r, uint32_t addr) {
    asm volatile("ldmatrix.sync.aligned.m8n8.x4.shared.b16 {%0,%1,%2,%3}, [%4];"
                 : "=r"(r[0]), "=r"(r[1]), "=r"(r[2]), "=r"(r[3]) : "r"(addr));
}
__device__ __forceinline__ void ldmx2(uint32_t* r, uint32_t addr) {
    asm volatile("ldmatrix.sync.aligned.m8n8.x2.shared.b16 {%0,%1}, [%2];"
                 : "=r"(r[0]), "=r"(r[1]) : "r"(addr));
}
__device__ __forceinline__ void hmma(float* d, const uint32_t* a, const uint32_t* b) {
    asm volatile(
        "mma.sync.aligned.m16n8k16.row.col.f32.f16.f16.f32 "
        "{%0,%1,%2,%3}, {%4,%5,%6,%7}, {%8,%9}, {%0,%1,%2,%3};"
        : "+f"(d[0]), "+f"(d[1]), "+f"(d[2]), "+f"(d[3])
        : "r"(a[0]), "r"(a[1]), "r"(a[2]), "r"(a[3]), "r"(b[0]), "r"(b[1]));
}
__device__ __forceinline__ void cpa16(uint32_t dst, const void* src) {
    asm volatile("cp.async.cg.shared.global [%0], [%1], 16;" :: "r"(dst), "l"(src));
}
#define CP_COMMIT() asm volatile("cp.async.commit_group;" ::: "memory")
template<int N> __device__ __forceinline__ void cp_wait() {
    asm volatile("cp.async.wait_group %0;" :: "n"(N) : "memory");
}
__device__ __forceinline__ float gelu_exact(float x) {
    return 0.5f * x * (1.0f + erff(x * 0.70710678118654752f));
}

struct GArg { const h16* A; const h16* B; float* C; h16* Ch; };

// ======================= fp16 HMMA GEMM, 3-stage cp.async =======================
// C[m,n] = sum_k A[m,k]*B[n,k]; fp16 in, fp32 accum. blockIdx.z selects arg set.
// Block tile 128 x BN, BK=32, warp tile 64x32.
// EPI: 0 = fp32 store, 3 = bias fp32 store, 4 = bias+GELU fp16 store.
template<int BN, int EPI>
__global__ __launch_bounds__(64*(BN/32))
void tgemm(GArg g0, GArg g1, int lda, int ldb, int ldc, int K,
           const float* bias0, const float* bias1)
{
    constexpr int WN = BN / 32;
    constexpr int T  = 64 * WN;
    constexpr int PK = 40;                    // padded k stride (elems), 80B
    constexpr int ASZ = 128 * PK * 2;         // bytes
    constexpr int BSZ = BN  * PK * 2;
    constexpr int STG = ASZ + BSZ;

    const GArg ga = blockIdx.z ? g1 : g0;
    const float* bias = blockIdx.z ? bias1 : bias0;

    extern __shared__ char smem[];
    const uint32_t base = smem_u32(smem);

    const int tid  = threadIdx.x;
    const int wid  = tid >> 5, lane = tid & 31;
    const int warp_m = wid & 1, warp_n = wid >> 1;
    const int m0 = blockIdx.y * 128;
    const int n0 = blockIdx.x * BN;

    float acc[4][4][4];
#pragma unroll
    for (int i = 0; i < 4; i++)
#pragma unroll
        for (int j = 0; j < 4; j++)
#pragma unroll
            for (int q = 0; q < 4; q++) acc[i][j][q] = 0.f;

    const int rA = (lane & 15);
    const int cA = (lane >> 4) * 8;
    const int l2 = lane & 15;
    const int rB = l2 & 7;
    const int cB = (l2 >> 3) * 8;

    auto load_tiles = [&](int k0, uint32_t aS, uint32_t bS) {
#pragma unroll
        for (int m = 0; m < 512 / T; m++) {
            int cid = tid + m * T;
            int row = cid >> 2, c4 = cid & 3;
            cpa16(aS + (row * PK + c4 * 8) * 2,
                  ga.A + (size_t)(m0 + row) * lda + k0 + c4 * 8);
        }
#pragma unroll
        for (int m = 0; m < (BN * 4) / T; m++) {
            int cid = tid + m * T;
            int row = cid >> 2, c4 = cid & 3;
            cpa16(bS + (row * PK + c4 * 8) * 2,
                  ga.B + (size_t)(n0 + row) * ldb + k0 + c4 * 8);
        }
    };

    const int nk = K / 32;
    load_tiles(0, base, base + ASZ);
    CP_COMMIT();
    load_tiles(32, base + STG, base + STG + ASZ);
    CP_COMMIT();

    for (int i = 0; i < nk; i++) {
        if (i < nk - 1) cp_wait<1>(); else cp_wait<0>();
        __syncthreads();
        if (i + 2 < nk) {
            int s = (i + 2) % 3;
            load_tiles((i + 2) * 32, base + s * STG, base + s * STG + ASZ);
            CP_COMMIT();
        }
        const uint32_t aS = base + (i % 3) * STG;
        const uint32_t bS = aS + ASZ;

#pragma unroll
        for (int kk = 0; kk < 32; kk += 16) {
            uint32_t Ar[4][4], Br[4][2];
            const int aoff = kk + cA;
            const int boff = kk + cB;
#pragma unroll
            for (int mf = 0; mf < 4; mf++)
                ldmx4(Ar[mf], aS + ((warp_m*64 + mf*16 + rA) * PK + aoff) * 2);
#pragma unroll
            for (int nf = 0; nf < 4; nf++)
                ldmx2(Br[nf], bS + ((warp_n*32 + nf*8 + rB) * PK + boff) * 2);
#pragma unroll
            for (int mf = 0; mf < 4; mf++)
#pragma unroll
                for (int nf = 0; nf < 4; nf++)
                    hmma(acc[mf][nf], Ar[mf], Br[nf]);
        }
    }

    // ---- epilogue ----
    const int rr = lane >> 2;
    const int cc = (lane & 3) * 2;
#pragma unroll
    for (int mf = 0; mf < 4; mf++) {
#pragma unroll
        for (int nf = 0; nf < 4; nf++) {
            int col = n0 + warp_n*32 + nf*8 + cc;
            float b0 = 0.f, b1 = 0.f;
            if (EPI == 3 || EPI == 4) { b0 = bias[col]; b1 = bias[col+1]; }
#pragma unroll
            for (int h = 0; h < 2; h++) {
                int row = m0 + warp_m*64 + mf*16 + rr + h*8;
                float v0 = acc[mf][nf][h*2+0];
                float v1 = acc[mf][nf][h*2+1];
                if (EPI == 3) {
                    *reinterpret_cast<float2*>(ga.C + (size_t)row * ldc + col) =
                        make_float2(v0 + b0, v1 + b1);
                } else if (EPI == 4) {
                    v0 = gelu_exact(v0 + b0); v1 = gelu_exact(v1 + b1);
                    *reinterpret_cast<__half2*>(ga.Ch + (size_t)row * ldc + col) =
                        __floats2half2_rn(v0, v1);
                } else {
                    *reinterpret_cast<float2*>(ga.C + (size_t)row * ldc + col) =
                        make_float2(v0, v1);
                }
            }
        }
    }
}

// ---------------- single launch: all fp32->fp16 conversions ----------------
#define SZ_X   (MROWS*DM)
#define SZ_IN  (2*DIN*DM)
#define SZ_XP  (64*DIN)
#define SZ_OP  (DM*DIN)
#define SZ_C1  (DFF*DM)
#define SZ_C2  (DM*DFF)
#define CV_TOTAL (SZ_X + 2*SZ_IN + 2*SZ_XP + 2*SZ_OP + SZ_C1 + SZ_C2)

__global__ void convert_all(const float* __restrict__ x,
                            const float* __restrict__ in1, const float* __restrict__ in2,
                            const float* __restrict__ xp1, const float* __restrict__ xp2,
                            const float* __restrict__ op1, const float* __restrict__ op2,
                            const float* __restrict__ c1,  const float* __restrict__ c2)
{
    long j = (long)blockIdx.x*256 + threadIdx.x;
    if (j < SZ_X)  { g_xh[j] = __float2half_rn(x[j]); return; }    j -= SZ_X;
    if (j < SZ_IN) { g_win1h[j] = __float2half_rn(in1[j]); return; } j -= SZ_IN;
    if (j < SZ_IN) { g_win2h[j] = __float2half_rn(in2[j]); return; } j -= SZ_IN;
    if (j < SZ_XP) { g_wxp1h[j] = __float2half_rn(xp1[j]); return; } j -= SZ_XP;
    if (j < SZ_XP) { g_wxp2h[j] = __float2half_rn(xp2[j]); return; } j -= SZ_XP;
    if (j < SZ_OP) { long r = j/DIN, k = j%DIN;
                     g_woh[r*2*DIN + k] = __float2half_rn(op1[j]); return; } j -= SZ_OP;
    if (j < SZ_OP) { long r = j/DIN, k = j%DIN;
                     g_woh[r*2*DIN + DIN + k] = __float2half_rn(op2[j]); return; } j -= SZ_OP;
    if (j < SZ_C1) { g_wc1h[j] = __float2half_rn(c1[j]); return; } j -= SZ_C1;
    if (j < SZ_C2) { g_wc2h[j] = __float2half_rn(c2[j]); }
}

// ---------------- prep: A = -exp(Alog) ----------------
__global__ void prep_kernel(const float* __restrict__ Alog1, const float* __restrict__ Alog2)
{
    int i = blockIdx.x*256 + threadIdx.x;
    if (i < DIN*DS) {
        g_A[i]          = -__expf(Alog1[i]);
        g_A[DIN*DS + i] = -__expf(Alog2[i]);
    }
}

// ---------------- depthwise causal conv (k=4) + bias + SiLU, rolling window -------------
// grid (DIN/256, Lq/64, 16): z = b + 8*dir. Each thread: one channel d, 64 timesteps.
__global__ __launch_bounds__(256)
void conv_kernel(const float* __restrict__ w1, const float* __restrict__ b1,
                 const float* __restrict__ w2, const float* __restrict__ b2)
{
    int d   = blockIdx.x*256 + threadIdx.x;
    int b   = blockIdx.z & 7;
    int dir = blockIdx.z >> 3;
    int T0  = blockIdx.y * 64;

    const float* xz = dir ? g_xz2 : g_xz1;
    const float* w  = dir ? w2 : w1;
    const float* cb = dir ? b2 : b1;
    float* xc       = dir ? g_xc2 : g_xc1;
    h16* xch        = dir ? g_xc2h : g_xc1h;

    const float4 wv = *reinterpret_cast<const float4*>(w + d*4);
    const float bias = cb[d];
    const float* X = xz + ((size_t)b*Lq)*(2*DIN) + d;   // xs column d
    const size_t rs = 2*DIN;

    if (dir == 0) {
        // out[t] = w3*x[t] + w2*x[t-1] + w1*x[t-2] + w0*x[t-3]
        float v0 = (T0-1 >= 0) ? X[(size_t)(T0-1)*rs] : 0.f;   // x[t-1]
        float v1 = (T0-2 >= 0) ? X[(size_t)(T0-2)*rs] : 0.f;   // x[t-2]
        float v2 = (T0-3 >= 0) ? X[(size_t)(T0-3)*rs] : 0.f;   // x[t-3]
#pragma unroll 4
        for (int t = T0; t < T0+64; t++) {
            float vn = X[(size_t)t*rs];
            float s = bias + wv.w*vn + wv.z*v0 + wv.y*v1 + wv.x*v2;
            v2 = v1; v1 = v0; v0 = vn;
            float r = s / (1.f + __expf(-s));
            size_t o = ((size_t)b*Lq + t)*DIN + d;
            xc[o] = r;
            xch[o] = __float2half_rn(r);
        }
    } else {
        // out[t] = w3*x[t] + w2*x[t+1] + w1*x[t+2] + w0*x[t+3]
        float v0 = X[(size_t)T0*rs];                              // x[t]
        float v1 = (T0+1 < Lq) ? X[(size_t)(T0+1)*rs] : 0.f;      // x[t+1]
        float v2 = (T0+2 < Lq) ? X[(size_t)(T0+2)*rs] : 0.f;      // x[t+2]
#pragma unroll 4
        for (int t = T0; t < T0+64; t++) {
            float vn = (t+3 < Lq) ? X[(size_t)(t+3)*rs] : 0.f;
            float s = bias + wv.w*v0 + wv.z*v1 + wv.y*v2 + wv.x*vn;
            v0 = v1; v1 = v2; v2 = vn;
            float r = s / (1.f + __expf(-s));
            size_t o = ((size_t)b*Lq + t)*DIN + d;
            xc[o] = r;
            xch[o] = __float2half_rn(r);
        }
    }
}

// ---------------- dt = softplus(xdbl[:, :32] @ W^T + b), tiled smem GEMM ----------------
// grid (DIN/128, MROWS/128, 2), 256 threads, 128x128 tile, K=32.
__global__ __launch_bounds__(256)
void dtg_kernel(const float* __restrict__ w1, const float* __restrict__ w2,
                const float* __restrict__ b1, const float* __restrict__ b2)
{
    int dir = blockIdx.z;
    const float* xdbl = dir ? g_xdbl2 : g_xdbl1;
    const float* W    = dir ? w2 : w1;         // (DIN, DTR) row-major
    const float* bias = dir ? b2 : b1;
    float* outp       = dir ? g_dt2 : g_dt1;

    __shared__ float sX[128][33];   // [row][k]
    __shared__ float sW[128][33];   // [dcol][k]

    const int tid = threadIdx.x;
    const int d0 = blockIdx.x*128, r0 = blockIdx.y*128;

#pragma unroll
    for (int i = 0; i < 16; i++) {
        int idx = tid + i*256;
        int r = idx >> 5, k = idx & 31;
        sX[r][k] = xdbl[(size_t)(r0+r)*64 + k];
    }
#pragma unroll
    for (int i = 0; i < 16; i++) {
        int idx = tid + i*256;
        int dd = idx >> 5, k = idx & 31;
        sW[dd][k] = W[(size_t)(d0+dd)*DTR + k];
    }
    __syncthreads();

    const int tx = tid & 15, ty = tid >> 4;
    float acc[8][8];
#pragma unroll
    for (int i = 0; i < 8; i++)
#pragma unroll
        for (int j = 0; j < 8; j++) acc[i][j] = 0.f;

#pragma unroll
    for (int k = 0; k < 32; k++) {
        float a[8], bb[8];
#pragma unroll
        for (int i = 0; i < 8; i++) a[i] = sX[ty + i*16][k];
#pragma unroll
        for (int j = 0; j < 8; j++) bb[j] = sW[tx + j*16][k];
#pragma unroll
        for (int i = 0; i < 8; i++)
#pragma unroll
            for (int j = 0; j < 8; j++) acc[i][j] = fmaf(a[i], bb[j], acc[i][j]);
    }

#pragma unroll
    for (int i = 0; i < 8; i++) {
#pragma unroll
        for (int j = 0; j < 8; j++) {
            int r = r0 + ty + i*16, c = d0 + tx + j*16;
            float s = acc[i][j] + bias[c];
            float sp = (s > 20.f) ? s : log1pf(__expf(s));
            outp[(size_t)r*DIN + c] = sp;
        }
    }
}

// ---------------- selective scan: 2 states/lane, 4 ch/warp, prefetch ----------------
// grid (1024, 2), 64 threads.
__global__ __launch_bounds__(64)
void scan_kernel(const float* __restrict__ D1, const float* __restrict__ D2)
{
    int dir = blockIdx.y;
    const float* dt   = dir ? g_dt2  : g_dt1;
    const float* xc   = dir ? g_xc2  : g_xc1;
    const float* xdbl = dir ? g_xdbl2: g_xdbl1;
    const float* xz   = dir ? g_xz2  : g_xz1;
    const float* Aexp = g_A + dir*DIN*DS;
    const float* Dv_  = dir ? D2 : D1;

    int warp = threadIdx.x >> 5, lane = threadIdx.x & 31;
    int sl  = lane & 7;                      // state lane (2 states each)
    int chl = lane >> 3;                     // channel within warp
    int c   = blockIdx.x*8 + warp*4 + chl;   // channels per dir: 8192
    int b   = c >> 10, d = c & (DIN-1);

    const float2 a2 = *(const float2*)(Aexp + d*DS + sl*2);
    const float Dd = Dv_[d];
    float hx = 0.f, hy = 0.f;
    const int rbase = b*Lq;
    const int step = dir ? -1 : 1;

    int t = dir ? (Lq-1) : 0;
    size_t row = rbase + t;
    float dtv = dt[row*DIN + d];
    float uv  = xc[row*DIN + d];
    float2 Bv = *(const float2*)(xdbl + row*64 + DTR + sl*2);
    float2 Cv = *(const float2*)(xdbl + row*64 + DTR + DS + sl*2);
    float zv  = xz[row*(2*DIN) + DIN + d];

    for (int i = 0; i < Lq; i++) {
        int tn = t + step;
        if (tn < 0) tn = 0; if (tn > Lq-1) tn = Lq-1;
        size_t rown = rbase + tn;
        // prefetch next
        float dtn = dt[rown*DIN + d];
        float un  = xc[rown*DIN + d];
        float2 Bn = *(const float2*)(xdbl + rown*64 + DTR + sl*2);
        float2 Cn = *(const float2*)(xdbl + rown*64 + DTR + DS + sl*2);
        float zn  = xz[rown*(2*DIN) + DIN + d];
        // compute current
        float du = dtv*uv;
        hx = fmaf(__expf(dtv*a2.x), hx, du*Bv.x);
        hy = fmaf(__expf(dtv*a2.y), hy, du*Bv.y);
        float p = hx*Cv.x + hy*Cv.y;
        p += __shfl_xor_sync(0xffffffffu, p, 1);
        p += __shfl_xor_sync(0xffffffffu, p, 2);
        p += __shfl_xor_sync(0xffffffffu, p, 4);
        if (sl == 0) {
            float yv = (p + uv*Dd) * (zv / (1.f + __expf(-zv)));
            g_yh[row*(2*DIN) + dir*DIN + d] = __float2half_rn(yv);
        }
        dtv = dtn; uv = un; Bv = Bn; Cv = Cn; zv = zn;
        t = tn; row = rown;
    }
}

// ---------------- LayerNorm: out = LN(a + b) * g + beta (+ optional fp16 copy) ---------
__global__ __launch_bounds__(256)
void ln_kernel(const float* __restrict__ a, const float* __restrict__ b,
               const float* __restrict__ g, const float* __restrict__ beta,
               float* __restrict__ out, h16* __restrict__ oh)
{
    int row  = blockIdx.x*8 + (threadIdx.x >> 5);
    int lane = threadIdx.x & 31;
    const float* pa = a + (size_t)row*DM;
    const float* pb = b + (size_t)row*DM;
    float v[16];
    float s = 0.f, s2 = 0.f;
#pragma unroll
    for (int i = 0; i < 16; i++) {
        int cix = lane + i*32;
        float x = pa[cix] + pb[cix];
        v[i] = x; s += x; s2 = fmaf(x, x, s2);
    }
#pragma unroll
    for (int off = 16; off > 0; off >>= 1) {
        s  += __shfl_xor_sync(0xffffffffu, s,  off);
        s2 += __shfl_xor_sync(0xffffffffu, s2, off);
    }
    float mean = s * (1.f/DM);
    float var  = s2 * (1.f/DM) - mean*mean;
    float inv  = rsqrtf(var + 1e-5f);
    float* po = out + (size_t)row*DM;
#pragma unroll
    for (int i = 0; i < 16; i++) {
        int cix = lane + i*32;
        float r = (v[i]-mean)*inv*g[cix] + beta[cix];
        po[cix] = r;
        if (oh) oh[(size_t)row*DM + cix] = __float2half_rn(r);
    }
}

// ---------------- launch ----------------
extern "C" void kernel_launch(void* const* d_in, const int* in_sizes, int n_in,
                              void* d_out, int out_size)
{
    const float* x       = (const float*)d_in[0];
    const float* in1_w   = (const float*)d_in[1];
    const float* conv1_w = (const float*)d_in[2];
    const float* conv1_b = (const float*)d_in[3];
    const float* xp1_w   = (const float*)d_in[4];
    const float* dtp1_w  = (const float*)d_in[5];
    const float* dtp1_b  = (const float*)d_in[6];
    const float* Alog1   = (const float*)d_in[7];
    const float* D1      = (const float*)d_in[8];
    const float* outp1_w = (const float*)d_in[9];
    const float* in2_w   = (const float*)d_in[10];
    const float* conv2_w = (const float*)d_in[11];
    const float* conv2_b = (const float*)d_in[12];
    const float* xp2_w   = (const float*)d_in[13];
    const float* dtp2_w  = (const float*)d_in[14];
    const float* dtp2_b  = (const float*)d_in[15];
    const float* Alog2   = (const float*)d_in[16];
    const float* D2      = (const float*)d_in[17];
    const float* outp2_w = (const float*)d_in[18];
    const float* c1_w    = (const float*)d_in[19];
    const float* c1_b    = (const float*)d_in[20];
    const float* c2_w    = (const float*)d_in[21];
    const float* c2_b    = (const float*)d_in[22];
    const float* ln1_g   = (const float*)d_in[23];
    const float* ln1_b   = (const float*)d_in[24];
    const float* ln2_g   = (const float*)d_in[25];
    const float* ln2_b   = (const float*)d_in[26];
    float* out = (float*)d_out;

    float *xz1,*xz2,*xdbl1,*xdbl2,*o,*xln,*yff;
    cudaGetSymbolAddress((void**)&xz1,  g_xz1);
    cudaGetSymbolAddress((void**)&xz2,  g_xz2);
    cudaGetSymbolAddress((void**)&xdbl1,g_xdbl1);
    cudaGetSymbolAddress((void**)&xdbl2,g_xdbl2);
    cudaGetSymbolAddress((void**)&o,    g_o);
    cudaGetSymbolAddress((void**)&xln,  g_xln);
    cudaGetSymbolAddress((void**)&yff,  g_yff);

    h16 *xh,*xc1h,*xc2h,*yh,*xlnh,*hffh;
    cudaGetSymbolAddress((void**)&xh,  g_xh);
    cudaGetSymbolAddress((void**)&xc1h,g_xc1h);
    cudaGetSymbolAddress((void**)&xc2h,g_xc2h);
    cudaGetSymbolAddress((void**)&yh,  g_yh);
    cudaGetSymbolAddress((void**)&xlnh,g_xlnh);
    cudaGetSymbolAddress((void**)&hffh,g_hffh);

    h16 *win1h,*win2h,*wxp1h,*wxp2h,*woh,*wc1h,*wc2h;
    cudaGetSymbolAddress((void**)&win1h,g_win1h);
    cudaGetSymbolAddress((void**)&win2h,g_win2h);
    cudaGetSymbolAddress((void**)&wxp1h,g_wxp1h);
    cudaGetSymbolAddress((void**)&wxp2h,g_wxp2h);
    cudaGetSymbolAddress((void**)&woh,  g_woh);
    cudaGetSymbolAddress((void**)&wc1h, g_wc1h);
    cudaGetSymbolAddress((void**)&wc2h, g_wc2h);

    // dyn smem: 3 stages x (A 10240 + B BN*80)
    const int SM128 = 3*(10240 + 10240);  // 61440
    const int SM64  = 3*(10240 + 5120);   // 46080
    cudaFuncSetAttribute(tgemm<128,0>, cudaFuncAttributeMaxDynamicSharedMemorySize, SM128);
    cudaFuncSetAttribute(tgemm<128,3>, cudaFuncAttributeMaxDynamicSharedMemorySize, SM128);
    cudaFuncSetAttribute(tgemm<128,4>, cudaFuncAttributeMaxDynamicSharedMemorySize, SM128);
    cudaFuncSetAttribute(tgemm<64,0>,  cudaFuncAttributeMaxDynamicSharedMemorySize, SM64);

    prep_kernel<<<64,256>>>(Alog1, Alog2);
    convert_all<<<(CV_TOTAL+255)/256,256>>>(x, in1_w, in2_w, xp1_w, xp2_w,
                                            outp1_w, outp2_w, c1_w, c2_w);

    // in_proj, both dirs in one launch: (8192x2048) = x @ W^T, K=512
    {
        dim3 g(2*DIN/128, MROWS/128, 2);
        GArg a0 = {xh, win1h, xz1, nullptr};
        GArg a1 = {xh, win2h, xz2, nullptr};
        tgemm<128,0><<<g,256,SM128>>>(a0, a1, DM, DM, 2*DIN, DM, nullptr, nullptr);
    }

    // depthwise conv + silu (rolling window)
    {
        dim3 g(DIN/256, Lq/64, 16);
        conv_kernel<<<g,256>>>(conv1_w, conv1_b, conv2_w, conv2_b);
    }

    // x_proj, both dirs: (8192x64) = xc @ xp_w^T, K=1024
    {
        dim3 g(1, MROWS/128, 2);
        GArg a0 = {xc1h, wxp1h, xdbl1, nullptr};
        GArg a1 = {xc2h, wxp2h, xdbl2, nullptr};
        tgemm<64,0><<<g,128,SM64>>>(a0, a1, DIN, DIN, 64, DIN, nullptr, nullptr);
    }

    // dt_proj + softplus (tiled)
    {
        dim3 g(DIN/128, MROWS/128, 2);
        dtg_kernel<<<g,256>>>(dtp1_w, dtp2_w, dtp1_b, dtp2_b);
    }

    // selective scan + gate -> fp16 y
    {
        dim3 gs(1024, 2);
        scan_kernel<<<gs,64>>>(D1, D2);
    }

    // out_proj fused: o = [y1|y2](8192x2048) @ fused_w^T, K=2048
    {
        dim3 g(DM/128, MROWS/128, 1);
        GArg a0 = {yh, woh, o, nullptr};
        tgemm<128,0><<<g,256,SM128>>>(a0, a0, 2*DIN, 2*DIN, DM, 2*DIN, nullptr, nullptr);
    }

    // LN1: xln = LN(o + x)  (+ fp16 copy)
    ln_kernel<<<MROWS/8,256>>>(o, x, ln1_g, ln1_b, xln, xlnh);

    // FFN
    {
        dim3 g1(DFF/128, MROWS/128, 1);
        GArg a0 = {xlnh, wc1h, nullptr, hffh};
        tgemm<128,4><<<g1,256,SM128>>>(a0, a0, DM, DM, DFF, DM, c1_b, c1_b);
        dim3 g2(DM/128, MROWS/128, 1);
        GArg a2 = {hffh, wc2h, yff, nullptr};
        tgemm<128,3><<<g2,256,SM128>>>(a2, a2, DFF, DFF, DM, DFF, c2_b, c2_b);
    }

    // LN2: out = LN(xln + yff)
    ln_kernel<<<MROWS/8,256>>>(xln, yff, ln2_g, ln2_b, out, nullptr);
}